// round 3
// baseline (speedup 1.0000x reference)
#include <cuda_runtime.h>
#include <cuda_bf16.h>
#include <math.h>

// ---------------- problem constants ----------------
#define BB 4
#define LL 512
#define VV 32000
#define DD 1024
#define HH 16
#define HD 64
#define NLAYER 2
#define EE 8
#define KK 2
#define FF 4096
#define SS (BB*LL)      // 2048
#define CAP 320
#define D3 (3*DD)       // 3072

// ---------------- static scratch ----------------
__device__ float g_x[SS*DD];
__device__ float g_qkv[SS*D3];
__device__ float g_q[SS*DD];
__device__ float g_k[SS*DD];
__device__ float g_vt[SS*DD];           // V transposed per head: [(b,h), d, l]
__device__ float g_av[SS*DD];
__device__ float g_sc[BB*HH*LL*LL];     // 64 MB
__device__ float g_attn[SS*DD];
__device__ float g_tmp[SS*DD];
__device__ float g_xe[EE*CAP*DD];
__device__ float g_hbuf[EE*CAP*FF];
__device__ float g_oe[EE*CAP*DD];
__device__ int   g_topi[SS*2];
__device__ float g_topw[SS*2];
__device__ int   g_slot[EE*CAP];
__device__ float g_slotw[EE*CAP];

// ---------------- reductions ----------------
__device__ __forceinline__ float blockReduceSum(float v){
    __shared__ float sh[32];
    int lane = threadIdx.x & 31, wid = threadIdx.x >> 5;
    int nw = (blockDim.x + 31) >> 5;
    #pragma unroll
    for (int o = 16; o > 0; o >>= 1) v += __shfl_down_sync(0xffffffffu, v, o);
    __syncthreads();
    if (lane == 0) sh[wid] = v;
    __syncthreads();
    if (wid == 0) {
        v = (lane < nw) ? sh[lane] : 0.f;
        #pragma unroll
        for (int o = 16; o > 0; o >>= 1) v += __shfl_down_sync(0xffffffffu, v, o);
        if (lane == 0) sh[0] = v;
    }
    __syncthreads();
    return sh[0];
}

__device__ __forceinline__ float blockReduceMax(float v){
    __shared__ float sh[32];
    int lane = threadIdx.x & 31, wid = threadIdx.x >> 5;
    int nw = (blockDim.x + 31) >> 5;
    #pragma unroll
    for (int o = 16; o > 0; o >>= 1) v = fmaxf(v, __shfl_down_sync(0xffffffffu, v, o));
    __syncthreads();
    if (lane == 0) sh[wid] = v;
    __syncthreads();
    if (wid == 0) {
        v = (lane < nw) ? sh[lane] : -1e30f;
        #pragma unroll
        for (int o = 16; o > 0; o >>= 1) v = fmaxf(v, __shfl_down_sync(0xffffffffu, v, o));
        if (lane == 0) sh[0] = v;
    }
    __syncthreads();
    return sh[0];
}

// ============================================================
// Tensor-core GEMM (tf32, 2-term split, pipelined):
//   C = act(alpha * A(MxK) * B(NxK)^T + bias)
// Block 128x128x32, 8 warps, warp tile 64x32, mma m16n8k8.
// smem stores (hi,lo) pairs as float2; register-prefetch double
// buffering hides gmem latency under the MMA block.
// ============================================================
#define GBM 128
#define GBN 128
#define GBK 32
#define LD2 36    // row stride in float2 units (32 data + 4 pad)

#define MMA_TF32(d, a, b) \
    asm volatile("mma.sync.aligned.m16n8k8.row.col.f32.tf32.tf32.f32 " \
        "{%0,%1,%2,%3},{%4,%5,%6,%7},{%8,%9},{%0,%1,%2,%3};" \
        : "+f"(d[0]), "+f"(d[1]), "+f"(d[2]), "+f"(d[3]) \
        : "r"(a[0]), "r"(a[1]), "r"(a[2]), "r"(a[3]), "r"(b[0]), "r"(b[1]))

__device__ __forceinline__ float2 splt(float v){
    unsigned h, l;
    asm("cvt.rna.tf32.f32 %0, %1;" : "=r"(h) : "f"(v));
    float hf = __uint_as_float(h);
    asm("cvt.rna.tf32.f32 %0, %1;" : "=r"(l) : "f"(v - hf));
    return make_float2(hf, __uint_as_float(l));
}

__global__ void __launch_bounds__(256, 1)
gemm_tc(const float* __restrict__ A, const float* __restrict__ Bm,
        const float* __restrict__ bias, float* __restrict__ C,
        int M, int N, int K, int lda, int ldb, int ldc,
        long aStride, long bStride, long cStride, long biasStride,
        float alpha, int relu, int causal)
{
    extern __shared__ float2 sm2[];
    float2* As = sm2;               // [GBM][LD2]
    float2* Bs = sm2 + GBM * LD2;   // [GBN][LD2]

    int m0 = blockIdx.x * GBM;
    int n0 = blockIdx.y * GBN;
    if (causal && n0 > m0 + GBM - 1) return;   // fully-masked causal block

    int z = blockIdx.z;
    A  += (long)z * aStride;
    Bm += (long)z * bStride;
    C  += (long)z * cStride;
    if (bias) bias += (long)z * biasStride;

    int tid = threadIdx.x;
    int wid = tid >> 5, lane = tid & 31;
    int wm = (wid & 1) * 64;        // warp m-origin
    int wn = (wid >> 1) * 32;       // warp n-origin

    float c[4][4][4];
    #pragma unroll
    for (int i = 0; i < 4; i++)
        #pragma unroll
        for (int j = 0; j < 4; j++)
            #pragma unroll
            for (int r = 0; r < 4; r++) c[i][j][r] = 0.f;

    int lrow = tid >> 3;           // 0..31
    int lcol = (tid & 7) * 4;      // 0..28

    float4 aR[4], bR[4];

    // ---- tile loaders (K is always a multiple of GBK) ----
    auto ldTiles = [&](int kt) {
        #pragma unroll
        for (int r = 0; r < 4; r++) {
            int row = lrow + r * 32;
            int gm = m0 + row;
            aR[r] = (gm < M) ? *(const float4*)(A + (long)gm * lda + kt + lcol)
                             : make_float4(0.f, 0.f, 0.f, 0.f);
            int gn = n0 + row;
            bR[r] = (gn < N) ? *(const float4*)(Bm + (long)gn * ldb + kt + lcol)
                             : make_float4(0.f, 0.f, 0.f, 0.f);
        }
    };
    auto stTiles = [&]() {
        #pragma unroll
        for (int r = 0; r < 4; r++) {
            int row = lrow + r * 32;
            float2 a0 = splt(aR[r].x), a1 = splt(aR[r].y), a2 = splt(aR[r].z), a3 = splt(aR[r].w);
            float4* da = (float4*)(As + row * LD2 + lcol);
            da[0] = make_float4(a0.x, a0.y, a1.x, a1.y);
            da[1] = make_float4(a2.x, a2.y, a3.x, a3.y);
            float2 b0 = splt(bR[r].x), b1 = splt(bR[r].y), b2 = splt(bR[r].z), b3 = splt(bR[r].w);
            float4* db = (float4*)(Bs + row * LD2 + lcol);
            db[0] = make_float4(b0.x, b0.y, b1.x, b1.y);
            db[1] = make_float4(b2.x, b2.y, b3.x, b3.y);
        }
    };

    // ---- prologue ----
    ldTiles(0);
    stTiles();
    __syncthreads();

    int ar = lane >> 2, acl = lane & 3;

    for (int kt = 0; kt < K; kt += GBK) {
        bool more = (kt + GBK) < K;
        if (more) ldTiles(kt + GBK);       // prefetch next tile into regs

        #pragma unroll
        for (int ks = 0; ks < GBK / 8; ks++) {
            int k0 = ks * 8 + acl;
            int k1 = k0 + 4;
            unsigned ah[4][4], al[4][4], bh[4][2], bl[4][2];
            #pragma unroll
            for (int i = 0; i < 4; i++) {
                int r0 = wm + i * 16 + ar;
                float2 p0 = As[r0 * LD2 + k0];
                float2 p1 = As[(r0 + 8) * LD2 + k0];
                float2 p2 = As[r0 * LD2 + k1];
                float2 p3 = As[(r0 + 8) * LD2 + k1];
                ah[i][0] = __float_as_uint(p0.x); al[i][0] = __float_as_uint(p0.y);
                ah[i][1] = __float_as_uint(p1.x); al[i][1] = __float_as_uint(p1.y);
                ah[i][2] = __float_as_uint(p2.x); al[i][2] = __float_as_uint(p2.y);
                ah[i][3] = __float_as_uint(p3.x); al[i][3] = __float_as_uint(p3.y);
            }
            #pragma unroll
            for (int j = 0; j < 4; j++) {
                int nr = wn + j * 8 + ar;
                float2 q0 = Bs[nr * LD2 + k0];
                float2 q1 = Bs[nr * LD2 + k1];
                bh[j][0] = __float_as_uint(q0.x); bl[j][0] = __float_as_uint(q0.y);
                bh[j][1] = __float_as_uint(q1.x); bl[j][1] = __float_as_uint(q1.y);
            }
            // three passes: 16 independent MMAs between accumulator reuses
            #pragma unroll
            for (int i = 0; i < 4; i++)
                #pragma unroll
                for (int j = 0; j < 4; j++)
                    MMA_TF32(c[i][j], ah[i], bh[j]);
            #pragma unroll
            for (int i = 0; i < 4; i++)
                #pragma unroll
                for (int j = 0; j < 4; j++)
                    MMA_TF32(c[i][j], ah[i], bl[j]);
            #pragma unroll
            for (int i = 0; i < 4; i++)
                #pragma unroll
                for (int j = 0; j < 4; j++)
                    MMA_TF32(c[i][j], al[i], bh[j]);
        }
        __syncthreads();
        if (more) {
            stTiles();
            __syncthreads();
        }
    }

    // ---- epilogue ----
    int cr = lane >> 2, cc = (lane & 3) * 2;
    #pragma unroll
    for (int i = 0; i < 4; i++) {
        #pragma unroll
        for (int j = 0; j < 4; j++) {
            int gn = n0 + wn + j * 8 + cc;
            #pragma unroll
            for (int half = 0; half < 2; half++) {
                int gm = m0 + wm + i * 16 + cr + half * 8;
                if (gm >= M) continue;
                float v0 = c[i][j][half * 2 + 0] * alpha;
                float v1 = c[i][j][half * 2 + 1] * alpha;
                if (bias) {
                    if (gn < N)     v0 += bias[gn];
                    if (gn + 1 < N) v1 += bias[gn + 1];
                }
                if (relu) { v0 = fmaxf(v0, 0.f); v1 = fmaxf(v1, 0.f); }
                if (gn + 1 < N) {
                    *(float2*)(C + (long)gm * ldc + gn) = make_float2(v0, v1);
                } else if (gn < N) {
                    C[(long)gm * ldc + gn] = v0;
                }
            }
        }
    }
}

// ---------------- embedding + positional encoding ----------------
__global__ void embed_kernel(const int* __restrict__ src, const float* __restrict__ emb,
                             float* __restrict__ x)
{
    long i = (long)blockIdx.x * 256 + threadIdx.x;
    int s = (int)(i >> 10);
    int d = (int)(i & 1023);
    int l = s & (LL - 1);
    int tok = src[s];
    int half2 = (d >> 1) * 2;
    float div = __expf(-(float)half2 * (logf(10000.f) / (float)DD));
    float arg = (float)l * div;
    float pe = (d & 1) ? cosf(arg) : sinf(arg);
    x[i] = emb[(long)tok * DD + d] * 32.0f + pe;
}

// ---------------- head split (V transposed) / merge ----------------
__global__ void split_heads(const float* __restrict__ qkv,
                            float* __restrict__ q, float* __restrict__ k, float* __restrict__ vt)
{
    long i = (long)blockIdx.x * 256 + threadIdx.x;
    int s = (int)(i >> 10);
    int dc = (int)(i & 1023);
    int h = dc >> 6;
    int d = dc & 63;
    int b = s >> 9;
    int l = s & 511;
    long srcoff = (long)s * D3 + h * HD + d;
    long dst = (((long)(b * HH + h) * LL) + l) * HD + d;
    q[dst] = qkv[srcoff];
    k[dst] = qkv[srcoff + DD];
    long vdst = (((long)(b * HH + h) * HD) + d) * LL + l;
    vt[vdst] = qkv[srcoff + 2 * DD];
}

__global__ void merge_heads(const float* __restrict__ av, float* __restrict__ out)
{
    long i = (long)blockIdx.x * 256 + threadIdx.x;
    int s = (int)(i >> 10);
    int dc = (int)(i & 1023);
    int h = dc >> 6;
    int d = dc & 63;
    int b = s >> 9;
    int l = s & 511;
    long srcoff = (((long)(b * HH + h) * LL) + l) * HD + d;
    out[i] = av[srcoff];
}

// ---------------- causal softmax (in place) ----------------
__global__ void softmax_causal(float* __restrict__ sc)
{
    int row = blockIdx.x;
    int q = row & (LL - 1);
    float* s = sc + (long)row * LL;
    int t = threadIdx.x;

    float mx = -1e30f;
    for (int k = t; k <= q; k += 128) mx = fmaxf(mx, s[k]);
    mx = blockReduceMax(mx);

    float sum = 0.f;
    for (int k = t; k <= q; k += 128) {
        float e = expf(s[k] - mx);
        s[k] = e;
        sum += e;
    }
    sum = blockReduceSum(sum);
    float inv = 1.f / sum;
    for (int k = t; k <= q; k += 128) s[k] *= inv;
    for (int k = q + 1 + t; k < LL; k += 128) s[k] = 0.f;
}

// ---------------- residual + layernorm ----------------
__global__ void add_ln(const float* __restrict__ a, const float* __restrict__ b,
                       const float* __restrict__ w, const float* __restrict__ bb,
                       float* __restrict__ out)
{
    int row = blockIdx.x;
    int t = threadIdx.x;
    const float* pa = a + (long)row * DD;
    const float* pb = b + (long)row * DD;
    float v[4];
    float s = 0.f;
    #pragma unroll
    for (int i = 0; i < 4; i++) {
        int d = t + i * 256;
        v[i] = pa[d] + pb[d];
        s += v[i];
    }
    s = blockReduceSum(s);
    float mean = s * (1.f / DD);
    float qq = 0.f;
    #pragma unroll
    for (int i = 0; i < 4; i++) {
        float dd = v[i] - mean;
        qq += dd * dd;
    }
    qq = blockReduceSum(qq);
    float inv = rsqrtf(qq * (1.f / DD) + 1e-5f);
    #pragma unroll
    for (int i = 0; i < 4; i++) {
        int d = t + i * 256;
        out[(long)row * DD + d] = (v[i] - mean) * inv * w[d] + bb[d];
    }
}

// ---------------- MoE gating ----------------
__global__ void gate_topk(const float* __restrict__ x, const float* __restrict__ gw,
                          const float* __restrict__ gb,
                          int* __restrict__ topi, float* __restrict__ topw)
{
    __shared__ float sh[EE * 256];
    int s = blockIdx.x, t = threadIdx.x;
    float p[EE];
    #pragma unroll
    for (int e = 0; e < EE; e++) p[e] = 0.f;
    for (int d = t; d < DD; d += 256) {
        float xv = x[(long)s * DD + d];
        #pragma unroll
        for (int e = 0; e < EE; e++) p[e] += xv * gw[e * DD + d];
    }
    #pragma unroll
    for (int e = 0; e < EE; e++) sh[e * 256 + t] = p[e];
    __syncthreads();
    for (int o = 128; o > 0; o >>= 1) {
        if (t < o) {
            #pragma unroll
            for (int e = 0; e < EE; e++) sh[e * 256 + t] += sh[e * 256 + t + o];
        }
        __syncthreads();
    }
    if (t == 0) {
        float lg[EE];
        float mx = -1e30f;
        #pragma unroll
        for (int e = 0; e < EE; e++) { lg[e] = sh[e * 256] + gb[e]; mx = fmaxf(mx, lg[e]); }
        float sum = 0.f;
        #pragma unroll
        for (int e = 0; e < EE; e++) { lg[e] = expf(lg[e] - mx); sum += lg[e]; }
        float invs = 1.f / sum;
        #pragma unroll
        for (int e = 0; e < EE; e++) lg[e] *= invs;
        int i0 = 0;
        #pragma unroll
        for (int e = 1; e < EE; e++) if (lg[e] > lg[i0]) i0 = e;
        int i1 = (i0 == 0) ? 1 : 0;
        #pragma unroll
        for (int e = 0; e < EE; e++) if (e != i0 && lg[e] > lg[i1]) i1 = e;
        float w0 = lg[i0], w1 = lg[i1];
        float ws = 1.f / (w0 + w1);
        topi[2 * s]     = i0;
        topi[2 * s + 1] = i1;
        topw[2 * s]     = w0 * ws;
        topw[2 * s + 1] = w1 * ws;
    }
}

// ---------------- capacity routing: parallel block scan per expert ----------------
__global__ void route_kernel(const int* __restrict__ topi, const float* __restrict__ topw,
                             int* __restrict__ slot, float* __restrict__ slotw)
{
    __shared__ int cnt[256];
    int e = blockIdx.x;
    int t = threadIdx.x;
    int base = t * 8;
    int loc[8]; float lw[8]; int c = 0;
    #pragma unroll
    for (int i = 0; i < 8; i++) {
        int s = base + i;
        float w = -1.f;
        if (topi[2 * s] == e) w = topw[2 * s];
        else if (topi[2 * s + 1] == e) w = topw[2 * s + 1];
        if (w >= 0.f) { loc[c] = s; lw[c] = w; c++; }
    }
    cnt[t] = c;
    __syncthreads();
    for (int off = 1; off < 256; off <<= 1) {
        int v = 0;
        if (t >= off) v = cnt[t - off];
        __syncthreads();
        cnt[t] += v;
        __syncthreads();
    }
    int start = cnt[t] - c;
    for (int i = 0; i < c; i++) {
        int pos = start + i;
        if (pos < CAP) {
            slot[e * CAP + pos]  = loc[i];
            slotw[e * CAP + pos] = lw[i];
        }
    }
    int total = cnt[255];
    __syncthreads();
    for (int p = total + t; p < CAP; p += 256) {
        slot[e * CAP + p]  = -1;
        slotw[e * CAP + p] = 0.f;
    }
}

__global__ void gather_xe(const float* __restrict__ x, const int* __restrict__ slot,
                          float* __restrict__ xe)
{
    int sl = blockIdx.x;
    int t = slot[sl];
    float* dst = xe + (long)sl * DD;
    if (t < 0) {
        for (int d = threadIdx.x; d < DD; d += 256) dst[d] = 0.f;
    } else {
        const float* srcp = x + (long)t * DD;
        for (int d = threadIdx.x; d < DD; d += 256) dst[d] = srcp[d];
    }
}

__global__ void scatter_oe(const float* __restrict__ oe, const int* __restrict__ slot,
                           const float* __restrict__ slotw, float* __restrict__ y)
{
    int sl = blockIdx.x;
    int t = slot[sl];
    if (t < 0) return;
    float w = slotw[sl];
    const float* srcp = oe + (long)sl * DD;
    float* dst = y + (long)t * DD;
    for (int d = threadIdx.x; d < DD; d += 256) atomicAdd(&dst[d], srcp[d] * w);
}

// ---------------- host launcher ----------------
static const int GEMM_SMEM = 2 * GBM * LD2 * (int)sizeof(float2);  // 73728 B

extern "C" void kernel_launch(void* const* d_in, const int* in_sizes, int n_in,
                              void* d_out, int out_size)
{
    const int*   src        = (const int*)  d_in[0];
    const float* emb        = (const float*)d_in[1];
    const float* in_proj_w  = (const float*)d_in[2];
    const float* in_proj_b  = (const float*)d_in[3];
    const float* out_proj_w = (const float*)d_in[4];
    const float* out_proj_b = (const float*)d_in[5];
    const float* ln1_w      = (const float*)d_in[6];
    const float* ln1_b      = (const float*)d_in[7];
    const float* ln2_w      = (const float*)d_in[8];
    const float* ln2_b      = (const float*)d_in[9];
    const float* gate_w     = (const float*)d_in[10];
    const float* gate_b     = (const float*)d_in[11];
    const float* w1         = (const float*)d_in[12];
    const float* b1         = (const float*)d_in[13];
    const float* w2         = (const float*)d_in[14];
    const float* b2         = (const float*)d_in[15];
    const float* dec_w      = (const float*)d_in[16];
    const float* dec_b      = (const float*)d_in[17];
    float* out = (float*)d_out;

    static int smem_set = 0;
    if (!smem_set) {
        cudaFuncSetAttribute(gemm_tc, cudaFuncAttributeMaxDynamicSharedMemorySize, GEMM_SMEM);
        smem_set = 1;
    }

    float *x, *qkv, *q, *k, *vt, *av, *sc, *attn, *tmp, *xe, *hbuf, *oe, *topw, *slotw;
    int *topi, *slot;
    cudaGetSymbolAddress((void**)&x,    g_x);
    cudaGetSymbolAddress((void**)&qkv,  g_qkv);
    cudaGetSymbolAddress((void**)&q,    g_q);
    cudaGetSymbolAddress((void**)&k,    g_k);
    cudaGetSymbolAddress((void**)&vt,   g_vt);
    cudaGetSymbolAddress((void**)&av,   g_av);
    cudaGetSymbolAddress((void**)&sc,   g_sc);
    cudaGetSymbolAddress((void**)&attn, g_attn);
    cudaGetSymbolAddress((void**)&tmp,  g_tmp);
    cudaGetSymbolAddress((void**)&xe,   g_xe);
    cudaGetSymbolAddress((void**)&hbuf, g_hbuf);
    cudaGetSymbolAddress((void**)&oe,   g_oe);
    cudaGetSymbolAddress((void**)&topi, g_topi);
    cudaGetSymbolAddress((void**)&topw, g_topw);
    cudaGetSymbolAddress((void**)&slot, g_slot);
    cudaGetSymbolAddress((void**)&slotw, g_slotw);

    embed_kernel<<<(SS * DD) / 256, 256>>>(src, emb, x);

    for (int l = 0; l < NLAYER; l++) {
        const float* wi = in_proj_w  + (long)l * D3 * DD;
        const float* bi = in_proj_b  + (long)l * D3;
        const float* wo = out_proj_w + (long)l * DD * DD;
        const float* bo = out_proj_b + (long)l * DD;
        const float* gw = gate_w     + (long)l * EE * DD;
        const float* gb = gate_b     + (long)l * EE;
        const float* w1l = w1        + (long)l * EE * FF * DD;
        const float* b1l = b1        + (long)l * EE * FF;
        const float* w2l = w2        + (long)l * EE * DD * FF;
        const float* b2l = b2        + (long)l * EE * DD;

        // qkv = x @ wi^T + bi   [2048 x 3072], K=1024
        gemm_tc<<<dim3(SS/GBM, D3/GBN, 1), 256, GEMM_SMEM>>>(x, wi, bi, qkv,
            SS, D3, DD, DD, DD, D3, 0, 0, 0, 0, 1.f, 0, 0);

        split_heads<<<(SS * DD) / 256, 256>>>(qkv, q, k, vt);

        // scores = q @ k^T / 8   batch=64, M=N=512, K=64, causal block skip
        gemm_tc<<<dim3(LL/GBM, LL/GBN, BB*HH), 256, GEMM_SMEM>>>(q, k, nullptr, sc,
            LL, LL, HD, HD, HD, LL,
            (long)LL*HD, (long)LL*HD, (long)LL*LL, 0, 0.125f, 0, 1);

        softmax_causal<<<BB * HH * LL, 128>>>(sc);

        // av = attn @ vt^T   batch=64, M=512, N=64, K=512
        gemm_tc<<<dim3(LL/GBM, 1, BB*HH), 256, GEMM_SMEM>>>(sc, vt, nullptr, av,
            LL, HD, LL, LL, LL, HD,
            (long)LL*LL, (long)HD*LL, (long)LL*HD, 0, 1.f, 0, 0);

        merge_heads<<<(SS * DD) / 256, 256>>>(av, attn);

        // proj = attn @ wo^T + bo   [2048 x 1024], K=1024
        gemm_tc<<<dim3(SS/GBM, DD/GBN, 1), 256, GEMM_SMEM>>>(attn, wo, bo, tmp,
            SS, DD, DD, DD, DD, DD, 0, 0, 0, 0, 1.f, 0, 0);

        add_ln<<<SS, 256>>>(x, tmp, ln1_w + l * DD, ln1_b + l * DD, x);

        // ---- MoE ----
        gate_topk<<<SS, 256>>>(x, gw, gb, topi, topw);
        route_kernel<<<EE, 256>>>(topi, topw, slot, slotw);
        gather_xe<<<EE * CAP, 256>>>(x, slot, xe);

        // h = relu(xe @ w1^T + b1)   batch=8, M=320, N=4096, K=1024
        gemm_tc<<<dim3((CAP+GBM-1)/GBM, FF/GBN, EE), 256, GEMM_SMEM>>>(xe, w1l, b1l, hbuf,
            CAP, FF, DD, DD, DD, FF,
            (long)CAP*DD, (long)FF*DD, (long)CAP*FF, FF, 1.f, 1, 0);

        // oe = h @ w2^T + b2   batch=8, M=320, N=1024, K=4096
        gemm_tc<<<dim3((CAP+GBM-1)/GBM, DD/GBN, EE), 256, GEMM_SMEM>>>(hbuf, w2l, b2l, oe,
            CAP, DD, FF, FF, FF, DD,
            (long)CAP*FF, (long)DD*FF, (long)CAP*DD, DD, 1.f, 0, 0);

        cudaMemsetAsync(tmp, 0, (size_t)SS * DD * sizeof(float), 0);
        scatter_oe<<<EE * CAP, 256>>>(oe, slot, slotw, tmp);

        add_ln<<<SS, 256>>>(x, tmp, ln2_w + l * DD, ln2_b + l * DD, x);
    }

    // logits = x @ dec_w^T + dec_b   [2048 x 32000], K=1024
    gemm_tc<<<dim3(SS/GBM, (VV+GBN-1)/GBN, 1), 256, GEMM_SMEM>>>(x, dec_w, dec_b, out,
        SS, VV, DD, DD, DD, VV, 0, 0, 0, 0, 1.f, 0, 0);
}

// round 4
// speedup vs baseline: 1.0232x; 1.0232x over previous
#include <cuda_runtime.h>
#include <cuda_bf16.h>
#include <math.h>

// ---------------- problem constants ----------------
#define BB 4
#define LL 512
#define VV 32000
#define DD 1024
#define HH 16
#define HD 64
#define NLAYER 2
#define EE 8
#define KK 2
#define FF 4096
#define SS (BB*LL)      // 2048
#define CAP 320
#define D3 (3*DD)       // 3072

// ---------------- static scratch ----------------
__device__ float g_x[SS*DD];
__device__ float g_qkv[SS*D3];
__device__ float g_q[SS*DD];
__device__ float g_k[SS*DD];
__device__ float g_vt[SS*DD];           // V transposed per head: [(b,h), d, l]
__device__ float g_av[SS*DD];
__device__ float g_sc[BB*HH*LL*LL];     // 64 MB
__device__ float g_attn[SS*DD];
__device__ float g_tmp[SS*DD];
__device__ float g_xe[EE*CAP*DD];
__device__ float g_hbuf[EE*CAP*FF];
__device__ float g_oe[EE*CAP*DD];
__device__ int   g_topi[SS*2];
__device__ float g_topw[SS*2];
__device__ int   g_slot[EE*CAP];
__device__ float g_slotw[EE*CAP];

// ---------------- reductions ----------------
__device__ __forceinline__ float blockReduceSum(float v){
    __shared__ float sh[32];
    int lane = threadIdx.x & 31, wid = threadIdx.x >> 5;
    int nw = (blockDim.x + 31) >> 5;
    #pragma unroll
    for (int o = 16; o > 0; o >>= 1) v += __shfl_down_sync(0xffffffffu, v, o);
    __syncthreads();
    if (lane == 0) sh[wid] = v;
    __syncthreads();
    if (wid == 0) {
        v = (lane < nw) ? sh[lane] : 0.f;
        #pragma unroll
        for (int o = 16; o > 0; o >>= 1) v += __shfl_down_sync(0xffffffffu, v, o);
        if (lane == 0) sh[0] = v;
    }
    __syncthreads();
    return sh[0];
}

__device__ __forceinline__ float blockReduceMax(float v){
    __shared__ float sh[32];
    int lane = threadIdx.x & 31, wid = threadIdx.x >> 5;
    int nw = (blockDim.x + 31) >> 5;
    #pragma unroll
    for (int o = 16; o > 0; o >>= 1) v = fmaxf(v, __shfl_down_sync(0xffffffffu, v, o));
    __syncthreads();
    if (lane == 0) sh[wid] = v;
    __syncthreads();
    if (wid == 0) {
        v = (lane < nw) ? sh[lane] : -1e30f;
        #pragma unroll
        for (int o = 16; o > 0; o >>= 1) v = fmaxf(v, __shfl_down_sync(0xffffffffu, v, o));
        if (lane == 0) sh[0] = v;
    }
    __syncthreads();
    return sh[0];
}

// ============================================================
// Tensor-core GEMM (tf32 2-term split, double-buffered smem):
//   C = act(alpha * A(MxK) * B(NxK)^T + bias)
// Block 128x128x32, 8 warps, warp tile 64x32, mma m16n8k8.
// Two smem buffers: MMAs on buf[cur] overlap the split+STS of
// tile k+1 into buf[cur^1]; ONE __syncthreads per K-iter.
// ============================================================
#define GBM 128
#define GBN 128
#define GBK 32
#define LD2 36    // row stride in float2 units (32 data + 4 pad)

#define MMA_TF32(d, a, b) \
    asm volatile("mma.sync.aligned.m16n8k8.row.col.f32.tf32.tf32.f32 " \
        "{%0,%1,%2,%3},{%4,%5,%6,%7},{%8,%9},{%0,%1,%2,%3};" \
        : "+f"(d[0]), "+f"(d[1]), "+f"(d[2]), "+f"(d[3]) \
        : "r"(a[0]), "r"(a[1]), "r"(a[2]), "r"(a[3]), "r"(b[0]), "r"(b[1]))

__device__ __forceinline__ float2 splt(float v){
    unsigned h, l;
    asm("cvt.rna.tf32.f32 %0, %1;" : "=r"(h) : "f"(v));
    float hf = __uint_as_float(h);
    asm("cvt.rna.tf32.f32 %0, %1;" : "=r"(l) : "f"(v - hf));
    return make_float2(hf, __uint_as_float(l));
}

__global__ void __launch_bounds__(256, 1)
gemm_tc(const float* __restrict__ A, const float* __restrict__ Bm,
        const float* __restrict__ bias, float* __restrict__ C,
        int M, int N, int K, int lda, int ldb, int ldc,
        long aStride, long bStride, long cStride, long biasStride,
        float alpha, int relu, int causal)
{
    extern __shared__ float2 sm2[];
    // buffers: [A0][B0][A1][B1], each GBM*LD2 float2
    int m0 = blockIdx.x * GBM;
    int n0 = blockIdx.y * GBN;
    if (causal && n0 > m0 + GBM - 1) return;   // fully-masked causal block

    int z = blockIdx.z;
    A  += (long)z * aStride;
    Bm += (long)z * bStride;
    C  += (long)z * cStride;
    if (bias) bias += (long)z * biasStride;

    int tid = threadIdx.x;
    int wid = tid >> 5, lane = tid & 31;
    int wm = (wid & 1) * 64;        // warp m-origin
    int wn = (wid >> 1) * 32;       // warp n-origin

    float c[4][4][4];
    #pragma unroll
    for (int i = 0; i < 4; i++)
        #pragma unroll
        for (int j = 0; j < 4; j++)
            #pragma unroll
            for (int r = 0; r < 4; r++) c[i][j][r] = 0.f;

    int lrow = tid >> 3;           // 0..31
    int lcol = (tid & 7) * 4;      // 0..28

    float4 aR[4], bR[4];

    auto ldTiles = [&](int kt) {
        #pragma unroll
        for (int r = 0; r < 4; r++) {
            int row = lrow + r * 32;
            int gm = m0 + row;
            aR[r] = (gm < M) ? *(const float4*)(A + (long)gm * lda + kt + lcol)
                             : make_float4(0.f, 0.f, 0.f, 0.f);
            int gn = n0 + row;
            bR[r] = (gn < N) ? *(const float4*)(Bm + (long)gn * ldb + kt + lcol)
                             : make_float4(0.f, 0.f, 0.f, 0.f);
        }
    };
    auto stTiles = [&](float2* As, float2* Bs) {
        #pragma unroll
        for (int r = 0; r < 4; r++) {
            int row = lrow + r * 32;
            float2 a0 = splt(aR[r].x), a1 = splt(aR[r].y), a2 = splt(aR[r].z), a3 = splt(aR[r].w);
            float4* da = (float4*)(As + row * LD2 + lcol);
            da[0] = make_float4(a0.x, a0.y, a1.x, a1.y);
            da[1] = make_float4(a2.x, a2.y, a3.x, a3.y);
            float2 b0 = splt(bR[r].x), b1 = splt(bR[r].y), b2 = splt(bR[r].z), b3 = splt(bR[r].w);
            float4* db = (float4*)(Bs + row * LD2 + lcol);
            db[0] = make_float4(b0.x, b0.y, b1.x, b1.y);
            db[1] = make_float4(b2.x, b2.y, b3.x, b3.y);
        }
    };

    // ---- prologue: fill buffer 0 ----
    ldTiles(0);
    stTiles(sm2, sm2 + GBM * LD2);
    __syncthreads();

    int ar = lane >> 2, acl = lane & 3;
    int cur = 0;

    for (int kt = 0; kt < K; kt += GBK) {
        bool more = (kt + GBK) < K;
        if (more) ldTiles(kt + GBK);       // prefetch next tile into regs

        const float2* As = sm2 + (cur ? 2 * GBM * LD2 : 0);
        const float2* Bs = As + GBM * LD2;

        #pragma unroll
        for (int ks = 0; ks < GBK / 8; ks++) {
            int k0 = ks * 8 + acl;
            int k1 = k0 + 4;
            unsigned ah[4][4], al[4][4], bh[4][2], bl[4][2];
            #pragma unroll
            for (int i = 0; i < 4; i++) {
                int r0 = wm + i * 16 + ar;
                float2 p0 = As[r0 * LD2 + k0];
                float2 p1 = As[(r0 + 8) * LD2 + k0];
                float2 p2 = As[r0 * LD2 + k1];
                float2 p3 = As[(r0 + 8) * LD2 + k1];
                ah[i][0] = __float_as_uint(p0.x); al[i][0] = __float_as_uint(p0.y);
                ah[i][1] = __float_as_uint(p1.x); al[i][1] = __float_as_uint(p1.y);
                ah[i][2] = __float_as_uint(p2.x); al[i][2] = __float_as_uint(p2.y);
                ah[i][3] = __float_as_uint(p3.x); al[i][3] = __float_as_uint(p3.y);
            }
            #pragma unroll
            for (int j = 0; j < 4; j++) {
                int nr = wn + j * 8 + ar;
                float2 q0 = Bs[nr * LD2 + k0];
                float2 q1 = Bs[nr * LD2 + k1];
                bh[j][0] = __float_as_uint(q0.x); bl[j][0] = __float_as_uint(q0.y);
                bh[j][1] = __float_as_uint(q1.x); bl[j][1] = __float_as_uint(q1.y);
            }
            #pragma unroll
            for (int i = 0; i < 4; i++)
                #pragma unroll
                for (int j = 0; j < 4; j++)
                    MMA_TF32(c[i][j], ah[i], bh[j]);
            #pragma unroll
            for (int i = 0; i < 4; i++)
                #pragma unroll
                for (int j = 0; j < 4; j++)
                    MMA_TF32(c[i][j], ah[i], bl[j]);
            #pragma unroll
            for (int i = 0; i < 4; i++)
                #pragma unroll
                for (int j = 0; j < 4; j++)
                    MMA_TF32(c[i][j], al[i], bh[j]);
        }

        if (more) {
            float2* Ad = sm2 + (cur ? 0 : 2 * GBM * LD2);
            stTiles(Ad, Ad + GBM * LD2);   // write OTHER buffer: overlaps peers' MMAs
        }
        __syncthreads();
        cur ^= 1;
    }

    // ---- epilogue ----
    int cr = lane >> 2, cc = (lane & 3) * 2;
    #pragma unroll
    for (int i = 0; i < 4; i++) {
        #pragma unroll
        for (int j = 0; j < 4; j++) {
            int gn = n0 + wn + j * 8 + cc;
            #pragma unroll
            for (int half = 0; half < 2; half++) {
                int gm = m0 + wm + i * 16 + cr + half * 8;
                if (gm >= M) continue;
                float v0 = c[i][j][half * 2 + 0] * alpha;
                float v1 = c[i][j][half * 2 + 1] * alpha;
                if (bias) {
                    if (gn < N)     v0 += bias[gn];
                    if (gn + 1 < N) v1 += bias[gn + 1];
                }
                if (relu) { v0 = fmaxf(v0, 0.f); v1 = fmaxf(v1, 0.f); }
                if (gn + 1 < N) {
                    *(float2*)(C + (long)gm * ldc + gn) = make_float2(v0, v1);
                } else if (gn < N) {
                    C[(long)gm * ldc + gn] = v0;
                }
            }
        }
    }
}

// ---------------- embedding + positional encoding ----------------
__global__ void embed_kernel(const int* __restrict__ src, const float* __restrict__ emb,
                             float* __restrict__ x)
{
    long i = (long)blockIdx.x * 256 + threadIdx.x;
    int s = (int)(i >> 10);
    int d = (int)(i & 1023);
    int l = s & (LL - 1);
    int tok = src[s];
    int half2 = (d >> 1) * 2;
    float div = __expf(-(float)half2 * (logf(10000.f) / (float)DD));
    float arg = (float)l * div;
    float pe = (d & 1) ? cosf(arg) : sinf(arg);
    x[i] = emb[(long)tok * DD + d] * 32.0f + pe;
}

// ---------------- head split (V transposed) / merge ----------------
__global__ void split_heads(const float* __restrict__ qkv,
                            float* __restrict__ q, float* __restrict__ k, float* __restrict__ vt)
{
    long i = (long)blockIdx.x * 256 + threadIdx.x;
    int s = (int)(i >> 10);
    int dc = (int)(i & 1023);
    int h = dc >> 6;
    int d = dc & 63;
    int b = s >> 9;
    int l = s & 511;
    long srcoff = (long)s * D3 + h * HD + d;
    long dst = (((long)(b * HH + h) * LL) + l) * HD + d;
    q[dst] = qkv[srcoff];
    k[dst] = qkv[srcoff + DD];
    long vdst = (((long)(b * HH + h) * HD) + d) * LL + l;
    vt[vdst] = qkv[srcoff + 2 * DD];
}

__global__ void merge_heads(const float* __restrict__ av, float* __restrict__ out)
{
    long i = (long)blockIdx.x * 256 + threadIdx.x;
    int s = (int)(i >> 10);
    int dc = (int)(i & 1023);
    int h = dc >> 6;
    int d = dc & 63;
    int b = s >> 9;
    int l = s & 511;
    long srcoff = (((long)(b * HH + h) * LL) + l) * HD + d;
    out[i] = av[srcoff];
}

// ---------------- causal softmax (in place) ----------------
__global__ void softmax_causal(float* __restrict__ sc)
{
    int row = blockIdx.x;
    int q = row & (LL - 1);
    float* s = sc + (long)row * LL;
    int t = threadIdx.x;

    float mx = -1e30f;
    for (int k = t; k <= q; k += 128) mx = fmaxf(mx, s[k]);
    mx = blockReduceMax(mx);

    float sum = 0.f;
    for (int k = t; k <= q; k += 128) {
        float e = expf(s[k] - mx);
        s[k] = e;
        sum += e;
    }
    sum = blockReduceSum(sum);
    float inv = 1.f / sum;
    for (int k = t; k <= q; k += 128) s[k] *= inv;
    for (int k = q + 1 + t; k < LL; k += 128) s[k] = 0.f;
}

// ---------------- residual + layernorm ----------------
__global__ void add_ln(const float* __restrict__ a, const float* __restrict__ b,
                       const float* __restrict__ w, const float* __restrict__ bb,
                       float* __restrict__ out)
{
    int row = blockIdx.x;
    int t = threadIdx.x;
    const float* pa = a + (long)row * DD;
    const float* pb = b + (long)row * DD;
    float v[4];
    float s = 0.f;
    #pragma unroll
    for (int i = 0; i < 4; i++) {
        int d = t + i * 256;
        v[i] = pa[d] + pb[d];
        s += v[i];
    }
    s = blockReduceSum(s);
    float mean = s * (1.f / DD);
    float qq = 0.f;
    #pragma unroll
    for (int i = 0; i < 4; i++) {
        float dd = v[i] - mean;
        qq += dd * dd;
    }
    qq = blockReduceSum(qq);
    float inv = rsqrtf(qq * (1.f / DD) + 1e-5f);
    #pragma unroll
    for (int i = 0; i < 4; i++) {
        int d = t + i * 256;
        out[(long)row * DD + d] = (v[i] - mean) * inv * w[d] + bb[d];
    }
}

// ---------------- MoE gating ----------------
__global__ void gate_topk(const float* __restrict__ x, const float* __restrict__ gw,
                          const float* __restrict__ gb,
                          int* __restrict__ topi, float* __restrict__ topw)
{
    __shared__ float sh[EE * 256];
    int s = blockIdx.x, t = threadIdx.x;
    float p[EE];
    #pragma unroll
    for (int e = 0; e < EE; e++) p[e] = 0.f;
    for (int d = t; d < DD; d += 256) {
        float xv = x[(long)s * DD + d];
        #pragma unroll
        for (int e = 0; e < EE; e++) p[e] += xv * gw[e * DD + d];
    }
    #pragma unroll
    for (int e = 0; e < EE; e++) sh[e * 256 + t] = p[e];
    __syncthreads();
    for (int o = 128; o > 0; o >>= 1) {
        if (t < o) {
            #pragma unroll
            for (int e = 0; e < EE; e++) sh[e * 256 + t] += sh[e * 256 + t + o];
        }
        __syncthreads();
    }
    if (t == 0) {
        float lg[EE];
        float mx = -1e30f;
        #pragma unroll
        for (int e = 0; e < EE; e++) { lg[e] = sh[e * 256] + gb[e]; mx = fmaxf(mx, lg[e]); }
        float sum = 0.f;
        #pragma unroll
        for (int e = 0; e < EE; e++) { lg[e] = expf(lg[e] - mx); sum += lg[e]; }
        float invs = 1.f / sum;
        #pragma unroll
        for (int e = 0; e < EE; e++) lg[e] *= invs;
        int i0 = 0;
        #pragma unroll
        for (int e = 1; e < EE; e++) if (lg[e] > lg[i0]) i0 = e;
        int i1 = (i0 == 0) ? 1 : 0;
        #pragma unroll
        for (int e = 0; e < EE; e++) if (e != i0 && lg[e] > lg[i1]) i1 = e;
        float w0 = lg[i0], w1 = lg[i1];
        float ws = 1.f / (w0 + w1);
        topi[2 * s]     = i0;
        topi[2 * s + 1] = i1;
        topw[2 * s]     = w0 * ws;
        topw[2 * s + 1] = w1 * ws;
    }
}

// ---------------- capacity routing: parallel block scan per expert ----------------
__global__ void route_kernel(const int* __restrict__ topi, const float* __restrict__ topw,
                             int* __restrict__ slot, float* __restrict__ slotw)
{
    __shared__ int cnt[256];
    int e = blockIdx.x;
    int t = threadIdx.x;
    int base = t * 8;
    int loc[8]; float lw[8]; int c = 0;
    #pragma unroll
    for (int i = 0; i < 8; i++) {
        int s = base + i;
        float w = -1.f;
        if (topi[2 * s] == e) w = topw[2 * s];
        else if (topi[2 * s + 1] == e) w = topw[2 * s + 1];
        if (w >= 0.f) { loc[c] = s; lw[c] = w; c++; }
    }
    cnt[t] = c;
    __syncthreads();
    for (int off = 1; off < 256; off <<= 1) {
        int v = 0;
        if (t >= off) v = cnt[t - off];
        __syncthreads();
        cnt[t] += v;
        __syncthreads();
    }
    int start = cnt[t] - c;
    for (int i = 0; i < c; i++) {
        int pos = start + i;
        if (pos < CAP) {
            slot[e * CAP + pos]  = loc[i];
            slotw[e * CAP + pos] = lw[i];
        }
    }
    int total = cnt[255];
    __syncthreads();
    for (int p = total + t; p < CAP; p += 256) {
        slot[e * CAP + p]  = -1;
        slotw[e * CAP + p] = 0.f;
    }
}

__global__ void gather_xe(const float* __restrict__ x, const int* __restrict__ slot,
                          float* __restrict__ xe)
{
    int sl = blockIdx.x;
    int t = slot[sl];
    float* dst = xe + (long)sl * DD;
    if (t < 0) {
        for (int d = threadIdx.x; d < DD; d += 256) dst[d] = 0.f;
    } else {
        const float* srcp = x + (long)t * DD;
        for (int d = threadIdx.x; d < DD; d += 256) dst[d] = srcp[d];
    }
}

__global__ void scatter_oe(const float* __restrict__ oe, const int* __restrict__ slot,
                           const float* __restrict__ slotw, float* __restrict__ y)
{
    int sl = blockIdx.x;
    int t = slot[sl];
    if (t < 0) return;
    float w = slotw[sl];
    const float* srcp = oe + (long)sl * DD;
    float* dst = y + (long)t * DD;
    for (int d = threadIdx.x; d < DD; d += 256) atomicAdd(&dst[d], srcp[d] * w);
}

// ---------------- host launcher ----------------
static const int GEMM_SMEM = 4 * GBM * LD2 * (int)sizeof(float2);  // 147456 B

extern "C" void kernel_launch(void* const* d_in, const int* in_sizes, int n_in,
                              void* d_out, int out_size)
{
    const int*   src        = (const int*)  d_in[0];
    const float* emb        = (const float*)d_in[1];
    const float* in_proj_w  = (const float*)d_in[2];
    const float* in_proj_b  = (const float*)d_in[3];
    const float* out_proj_w = (const float*)d_in[4];
    const float* out_proj_b = (const float*)d_in[5];
    const float* ln1_w      = (const float*)d_in[6];
    const float* ln1_b      = (const float*)d_in[7];
    const float* ln2_w      = (const float*)d_in[8];
    const float* ln2_b      = (const float*)d_in[9];
    const float* gate_w     = (const float*)d_in[10];
    const float* gate_b     = (const float*)d_in[11];
    const float* w1         = (const float*)d_in[12];
    const float* b1         = (const float*)d_in[13];
    const float* w2         = (const float*)d_in[14];
    const float* b2         = (const float*)d_in[15];
    const float* dec_w      = (const float*)d_in[16];
    const float* dec_b      = (const float*)d_in[17];
    float* out = (float*)d_out;

    static int smem_set = 0;
    if (!smem_set) {
        cudaFuncSetAttribute(gemm_tc, cudaFuncAttributeMaxDynamicSharedMemorySize, GEMM_SMEM);
        smem_set = 1;
    }

    float *x, *qkv, *q, *k, *vt, *av, *sc, *attn, *tmp, *xe, *hbuf, *oe, *topw, *slotw;
    int *topi, *slot;
    cudaGetSymbolAddress((void**)&x,    g_x);
    cudaGetSymbolAddress((void**)&qkv,  g_qkv);
    cudaGetSymbolAddress((void**)&q,    g_q);
    cudaGetSymbolAddress((void**)&k,    g_k);
    cudaGetSymbolAddress((void**)&vt,   g_vt);
    cudaGetSymbolAddress((void**)&av,   g_av);
    cudaGetSymbolAddress((void**)&sc,   g_sc);
    cudaGetSymbolAddress((void**)&attn, g_attn);
    cudaGetSymbolAddress((void**)&tmp,  g_tmp);
    cudaGetSymbolAddress((void**)&xe,   g_xe);
    cudaGetSymbolAddress((void**)&hbuf, g_hbuf);
    cudaGetSymbolAddress((void**)&oe,   g_oe);
    cudaGetSymbolAddress((void**)&topi, g_topi);
    cudaGetSymbolAddress((void**)&topw, g_topw);
    cudaGetSymbolAddress((void**)&slot, g_slot);
    cudaGetSymbolAddress((void**)&slotw, g_slotw);

    embed_kernel<<<(SS * DD) / 256, 256>>>(src, emb, x);

    for (int l = 0; l < NLAYER; l++) {
        const float* wi = in_proj_w  + (long)l * D3 * DD;
        const float* bi = in_proj_b  + (long)l * D3;
        const float* wo = out_proj_w + (long)l * DD * DD;
        const float* bo = out_proj_b + (long)l * DD;
        const float* gw = gate_w     + (long)l * EE * DD;
        const float* gb = gate_b     + (long)l * EE;
        const float* w1l = w1        + (long)l * EE * FF * DD;
        const float* b1l = b1        + (long)l * EE * FF;
        const float* w2l = w2        + (long)l * EE * DD * FF;
        const float* b2l = b2        + (long)l * EE * DD;

        // qkv = x @ wi^T + bi   [2048 x 3072], K=1024
        gemm_tc<<<dim3(SS/GBM, D3/GBN, 1), 256, GEMM_SMEM>>>(x, wi, bi, qkv,
            SS, D3, DD, DD, DD, D3, 0, 0, 0, 0, 1.f, 0, 0);

        split_heads<<<(SS * DD) / 256, 256>>>(qkv, q, k, vt);

        // scores = q @ k^T / 8   batch=64, M=N=512, K=64, causal block skip
        gemm_tc<<<dim3(LL/GBM, LL/GBN, BB*HH), 256, GEMM_SMEM>>>(q, k, nullptr, sc,
            LL, LL, HD, HD, HD, LL,
            (long)LL*HD, (long)LL*HD, (long)LL*LL, 0, 0.125f, 0, 1);

        softmax_causal<<<BB * HH * LL, 128>>>(sc);

        // av = attn @ vt^T   batch=64, M=512, N=64, K=512
        gemm_tc<<<dim3(LL/GBM, 1, BB*HH), 256, GEMM_SMEM>>>(sc, vt, nullptr, av,
            LL, HD, LL, LL, LL, HD,
            (long)LL*LL, (long)HD*LL, (long)LL*HD, 0, 1.f, 0, 0);

        merge_heads<<<(SS * DD) / 256, 256>>>(av, attn);

        // proj = attn @ wo^T + bo   [2048 x 1024], K=1024
        gemm_tc<<<dim3(SS/GBM, DD/GBN, 1), 256, GEMM_SMEM>>>(attn, wo, bo, tmp,
            SS, DD, DD, DD, DD, DD, 0, 0, 0, 0, 1.f, 0, 0);

        add_ln<<<SS, 256>>>(x, tmp, ln1_w + l * DD, ln1_b + l * DD, x);

        // ---- MoE ----
        gate_topk<<<SS, 256>>>(x, gw, gb, topi, topw);
        route_kernel<<<EE, 256>>>(topi, topw, slot, slotw);
        gather_xe<<<EE * CAP, 256>>>(x, slot, xe);

        // h = relu(xe @ w1^T + b1)   batch=8, M=320, N=4096, K=1024
        gemm_tc<<<dim3((CAP+GBM-1)/GBM, FF/GBN, EE), 256, GEMM_SMEM>>>(xe, w1l, b1l, hbuf,
            CAP, FF, DD, DD, DD, FF,
            (long)CAP*DD, (long)FF*DD, (long)CAP*FF, FF, 1.f, 1, 0);

        // oe = h @ w2^T + b2   batch=8, M=320, N=1024, K=4096
        gemm_tc<<<dim3((CAP+GBM-1)/GBM, DD/GBN, EE), 256, GEMM_SMEM>>>(hbuf, w2l, b2l, oe,
            CAP, DD, FF, FF, FF, DD,
            (long)CAP*FF, (long)DD*FF, (long)CAP*DD, DD, 1.f, 0, 0);

        cudaMemsetAsync(tmp, 0, (size_t)SS * DD * sizeof(float), 0);
        scatter_oe<<<EE * CAP, 256>>>(oe, slot, slotw, tmp);

        add_ln<<<SS, 256>>>(x, tmp, ln2_w + l * DD, ln2_b + l * DD, x);
    }

    // logits = x @ dec_w^T + dec_b   [2048 x 32000], K=1024
    gemm_tc<<<dim3(SS/GBM, (VV+GBN-1)/GBN, 1), 256, GEMM_SMEM>>>(x, dec_w, dec_b, out,
        SS, VV, DD, DD, DD, VV, 0, 0, 0, 0, 1.f, 0, 0);
}

// round 5
// speedup vs baseline: 2.0466x; 2.0003x over previous
#include <cuda_runtime.h>
#include <cuda_bf16.h>
#include <math.h>

// ---------------- problem constants ----------------
#define BB 4
#define LL 512
#define VV 32000
#define DD 1024
#define HH 16
#define HD 64
#define NLAYER 2
#define EE 8
#define KK 2
#define FF 4096
#define SS (BB*LL)      // 2048
#define CAP 320
#define D3 (3*DD)       // 3072

// ---------------- static scratch ----------------
__device__ float g_x[SS*DD];
__device__ float g_qkv[SS*D3];
__device__ float g_q[SS*DD];
__device__ float g_k[SS*DD];
__device__ float g_vt[SS*DD];           // V transposed per head: [(b,h), d, l]
__device__ float g_av[SS*DD];
__device__ float g_sc[BB*HH*LL*LL];     // 64 MB
__device__ float g_attn[SS*DD];
__device__ float g_tmp[SS*DD];
__device__ float g_xe[EE*CAP*DD];
__device__ float g_hbuf[EE*CAP*FF];
__device__ float g_oe[EE*CAP*DD];
__device__ int   g_topi[SS*2];
__device__ float g_topw[SS*2];
__device__ int   g_slot[EE*CAP];
__device__ float g_slotw[EE*CAP];

// ---------------- reductions ----------------
__device__ __forceinline__ float blockReduceSum(float v){
    __shared__ float sh[32];
    int lane = threadIdx.x & 31, wid = threadIdx.x >> 5;
    int nw = (blockDim.x + 31) >> 5;
    #pragma unroll
    for (int o = 16; o > 0; o >>= 1) v += __shfl_down_sync(0xffffffffu, v, o);
    __syncthreads();
    if (lane == 0) sh[wid] = v;
    __syncthreads();
    if (wid == 0) {
        v = (lane < nw) ? sh[lane] : 0.f;
        #pragma unroll
        for (int o = 16; o > 0; o >>= 1) v += __shfl_down_sync(0xffffffffu, v, o);
        if (lane == 0) sh[0] = v;
    }
    __syncthreads();
    return sh[0];
}

__device__ __forceinline__ float blockReduceMax(float v){
    __shared__ float sh[32];
    int lane = threadIdx.x & 31, wid = threadIdx.x >> 5;
    int nw = (blockDim.x + 31) >> 5;
    #pragma unroll
    for (int o = 16; o > 0; o >>= 1) v = fmaxf(v, __shfl_down_sync(0xffffffffu, v, o));
    __syncthreads();
    if (lane == 0) sh[wid] = v;
    __syncthreads();
    if (wid == 0) {
        v = (lane < nw) ? sh[lane] : -1e30f;
        #pragma unroll
        for (int o = 16; o > 0; o >>= 1) v = fmaxf(v, __shfl_down_sync(0xffffffffu, v, o));
        if (lane == 0) sh[0] = v;
    }
    __syncthreads();
    return sh[0];
}

// ============================================================
// Tensor-core GEMM, bf16x3 precision split on m16n8k16:
//   C = act(alpha * A(MxK) * B(NxK)^T + bias)
// Block 128x128x32, 8 warps, warp tile 64x32.
// A,B split into bf16 (hi, lo); D += Ah*Bh + Ah*Bl + Al*Bh.
// smem: per-tile [128 rows][16 k-pairs packed bf16x2] stride 20
// words (stride mod 32 == 4 -> conflict-free fragment loads).
// ============================================================
#define GBM 128
#define GBN 128
#define GBK 32
#define LDW 20    // row stride in 32-bit words (16 pairs + 4 pad)

#define MMA_BF16(d, a, b) \
    asm volatile("mma.sync.aligned.m16n8k16.row.col.f32.bf16.bf16.f32 " \
        "{%0,%1,%2,%3},{%4,%5,%6,%7},{%8,%9},{%0,%1,%2,%3};" \
        : "+f"(d[0]), "+f"(d[1]), "+f"(d[2]), "+f"(d[3]) \
        : "r"(a[0]), "r"(a[1]), "r"(a[2]), "r"(a[3]), "r"(b[0]), "r"(b[1]))

// split (x,y) into packed bf16x2 hi and lo words (low 16 bits = x)
__device__ __forceinline__ void splt2(float x, float y, unsigned& hi, unsigned& lo){
    __nv_bfloat162 H, L;
    H.x = __float2bfloat16_rn(x);
    H.y = __float2bfloat16_rn(y);
    L.x = __float2bfloat16_rn(x - __bfloat162float(H.x));
    L.y = __float2bfloat16_rn(y - __bfloat162float(H.y));
    hi = *(unsigned*)&H;
    lo = *(unsigned*)&L;
}

__global__ void __launch_bounds__(256)
gemm_tc(const float* __restrict__ A, const float* __restrict__ Bm,
        const float* __restrict__ bias, float* __restrict__ C,
        int M, int N, int K, int lda, int ldb, int ldc,
        long aStride, long bStride, long cStride, long biasStride,
        float alpha, int relu, int causal)
{
    __shared__ unsigned sAh[GBM * LDW];
    __shared__ unsigned sAl[GBM * LDW];
    __shared__ unsigned sBh[GBN * LDW];
    __shared__ unsigned sBl[GBN * LDW];

    int m0 = blockIdx.x * GBM;
    int n0 = blockIdx.y * GBN;
    if (causal && n0 > m0 + GBM - 1) return;   // fully-masked causal block

    int z = blockIdx.z;
    A  += (long)z * aStride;
    Bm += (long)z * bStride;
    C  += (long)z * cStride;
    if (bias) bias += (long)z * biasStride;

    int tid = threadIdx.x;
    int wid = tid >> 5, lane = tid & 31;
    int wm = (wid & 1) * 64;        // warp m-origin
    int wn = (wid >> 1) * 32;       // warp n-origin

    float c[4][4][4];
    #pragma unroll
    for (int i = 0; i < 4; i++)
        #pragma unroll
        for (int j = 0; j < 4; j++)
            #pragma unroll
            for (int r = 0; r < 4; r++) c[i][j][r] = 0.f;

    int lrow = tid >> 3;           // 0..31
    int lcol = (tid & 7) * 4;      // gmem k offset: 0,4,...,28
    int kp0  = (tid & 7) * 2;      // smem pair index: 0,2,...,14

    int ar = lane >> 2, acl = lane & 3;

    for (int kt = 0; kt < K; kt += GBK) {
        // ---- load + split + store tiles ----
        #pragma unroll
        for (int r = 0; r < 4; r++) {
            int row = lrow + r * 32;
            int gm = m0 + row;
            float4 va = (gm < M) ? *(const float4*)(A + (long)gm * lda + kt + lcol)
                                 : make_float4(0.f, 0.f, 0.f, 0.f);
            unsigned h0, l0, h1, l1;
            splt2(va.x, va.y, h0, l0);
            splt2(va.z, va.w, h1, l1);
            sAh[row * LDW + kp0]     = h0;
            sAh[row * LDW + kp0 + 1] = h1;
            sAl[row * LDW + kp0]     = l0;
            sAl[row * LDW + kp0 + 1] = l1;

            int gn = n0 + row;
            float4 vb = (gn < N) ? *(const float4*)(Bm + (long)gn * ldb + kt + lcol)
                                 : make_float4(0.f, 0.f, 0.f, 0.f);
            splt2(vb.x, vb.y, h0, l0);
            splt2(vb.z, vb.w, h1, l1);
            sBh[row * LDW + kp0]     = h0;
            sBh[row * LDW + kp0 + 1] = h1;
            sBl[row * LDW + kp0]     = l0;
            sBl[row * LDW + kp0 + 1] = l1;
        }
        __syncthreads();

        // ---- two k16 chunks per tile ----
        #pragma unroll
        for (int ks = 0; ks < 2; ks++) {
            int kb = ks * 8 + acl;
            unsigned ah[4][4], al[4][4], bh[4][2], bl[4][2];
            #pragma unroll
            for (int i = 0; i < 4; i++) {
                int r0 = (wm + i * 16 + ar) * LDW;
                int r1 = r0 + 8 * LDW;
                ah[i][0] = sAh[r0 + kb];     al[i][0] = sAl[r0 + kb];
                ah[i][1] = sAh[r1 + kb];     al[i][1] = sAl[r1 + kb];
                ah[i][2] = sAh[r0 + kb + 4]; al[i][2] = sAl[r0 + kb + 4];
                ah[i][3] = sAh[r1 + kb + 4]; al[i][3] = sAl[r1 + kb + 4];
            }
            #pragma unroll
            for (int j = 0; j < 4; j++) {
                int nr = (wn + j * 8 + ar) * LDW;
                bh[j][0] = sBh[nr + kb];     bl[j][0] = sBl[nr + kb];
                bh[j][1] = sBh[nr + kb + 4]; bl[j][1] = sBl[nr + kb + 4];
            }
            #pragma unroll
            for (int i = 0; i < 4; i++)
                #pragma unroll
                for (int j = 0; j < 4; j++)
                    MMA_BF16(c[i][j], ah[i], bh[j]);
            #pragma unroll
            for (int i = 0; i < 4; i++)
                #pragma unroll
                for (int j = 0; j < 4; j++)
                    MMA_BF16(c[i][j], ah[i], bl[j]);
            #pragma unroll
            for (int i = 0; i < 4; i++)
                #pragma unroll
                for (int j = 0; j < 4; j++)
                    MMA_BF16(c[i][j], al[i], bh[j]);
        }
        __syncthreads();
    }

    // ---- epilogue ----
    int cr = lane >> 2, cc = (lane & 3) * 2;
    #pragma unroll
    for (int i = 0; i < 4; i++) {
        #pragma unroll
        for (int j = 0; j < 4; j++) {
            int gn = n0 + wn + j * 8 + cc;
            #pragma unroll
            for (int half = 0; half < 2; half++) {
                int gm = m0 + wm + i * 16 + cr + half * 8;
                if (gm >= M) continue;
                float v0 = c[i][j][half * 2 + 0] * alpha;
                float v1 = c[i][j][half * 2 + 1] * alpha;
                if (bias) {
                    if (gn < N)     v0 += bias[gn];
                    if (gn + 1 < N) v1 += bias[gn + 1];
                }
                if (relu) { v0 = fmaxf(v0, 0.f); v1 = fmaxf(v1, 0.f); }
                if (gn + 1 < N) {
                    *(float2*)(C + (long)gm * ldc + gn) = make_float2(v0, v1);
                } else if (gn < N) {
                    C[(long)gm * ldc + gn] = v0;
                }
            }
        }
    }
}

// ---------------- embedding + positional encoding ----------------
__global__ void embed_kernel(const int* __restrict__ src, const float* __restrict__ emb,
                             float* __restrict__ x)
{
    long i = (long)blockIdx.x * 256 + threadIdx.x;
    int s = (int)(i >> 10);
    int d = (int)(i & 1023);
    int l = s & (LL - 1);
    int tok = src[s];
    int half2 = (d >> 1) * 2;
    float div = __expf(-(float)half2 * (logf(10000.f) / (float)DD));
    float arg = (float)l * div;
    float pe = (d & 1) ? cosf(arg) : sinf(arg);
    x[i] = emb[(long)tok * DD + d] * 32.0f + pe;
}

// ---------------- head split (V transposed) / merge ----------------
__global__ void split_heads(const float* __restrict__ qkv,
                            float* __restrict__ q, float* __restrict__ k, float* __restrict__ vt)
{
    long i = (long)blockIdx.x * 256 + threadIdx.x;
    int s = (int)(i >> 10);
    int dc = (int)(i & 1023);
    int h = dc >> 6;
    int d = dc & 63;
    int b = s >> 9;
    int l = s & 511;
    long srcoff = (long)s * D3 + h * HD + d;
    long dst = (((long)(b * HH + h) * LL) + l) * HD + d;
    q[dst] = qkv[srcoff];
    k[dst] = qkv[srcoff + DD];
    long vdst = (((long)(b * HH + h) * HD) + d) * LL + l;
    vt[vdst] = qkv[srcoff + 2 * DD];
}

__global__ void merge_heads(const float* __restrict__ av, float* __restrict__ out)
{
    long i = (long)blockIdx.x * 256 + threadIdx.x;
    int s = (int)(i >> 10);
    int dc = (int)(i & 1023);
    int h = dc >> 6;
    int d = dc & 63;
    int b = s >> 9;
    int l = s & 511;
    long srcoff = (((long)(b * HH + h) * LL) + l) * HD + d;
    out[i] = av[srcoff];
}

// ---------------- causal softmax (in place) ----------------
__global__ void softmax_causal(float* __restrict__ sc)
{
    int row = blockIdx.x;
    int q = row & (LL - 1);
    float* s = sc + (long)row * LL;
    int t = threadIdx.x;

    float mx = -1e30f;
    for (int k = t; k <= q; k += 128) mx = fmaxf(mx, s[k]);
    mx = blockReduceMax(mx);

    float sum = 0.f;
    for (int k = t; k <= q; k += 128) {
        float e = expf(s[k] - mx);
        s[k] = e;
        sum += e;
    }
    sum = blockReduceSum(sum);
    float inv = 1.f / sum;
    for (int k = t; k <= q; k += 128) s[k] *= inv;
    for (int k = q + 1 + t; k < LL; k += 128) s[k] = 0.f;
}

// ---------------- residual + layernorm ----------------
__global__ void add_ln(const float* __restrict__ a, const float* __restrict__ b,
                       const float* __restrict__ w, const float* __restrict__ bb,
                       float* __restrict__ out)
{
    int row = blockIdx.x;
    int t = threadIdx.x;
    const float* pa = a + (long)row * DD;
    const float* pb = b + (long)row * DD;
    float v[4];
    float s = 0.f;
    #pragma unroll
    for (int i = 0; i < 4; i++) {
        int d = t + i * 256;
        v[i] = pa[d] + pb[d];
        s += v[i];
    }
    s = blockReduceSum(s);
    float mean = s * (1.f / DD);
    float qq = 0.f;
    #pragma unroll
    for (int i = 0; i < 4; i++) {
        float dd = v[i] - mean;
        qq += dd * dd;
    }
    qq = blockReduceSum(qq);
    float inv = rsqrtf(qq * (1.f / DD) + 1e-5f);
    #pragma unroll
    for (int i = 0; i < 4; i++) {
        int d = t + i * 256;
        out[(long)row * DD + d] = (v[i] - mean) * inv * w[d] + bb[d];
    }
}

// ---------------- MoE gating ----------------
__global__ void gate_topk(const float* __restrict__ x, const float* __restrict__ gw,
                          const float* __restrict__ gb,
                          int* __restrict__ topi, float* __restrict__ topw)
{
    __shared__ float sh[EE * 256];
    int s = blockIdx.x, t = threadIdx.x;
    float p[EE];
    #pragma unroll
    for (int e = 0; e < EE; e++) p[e] = 0.f;
    for (int d = t; d < DD; d += 256) {
        float xv = x[(long)s * DD + d];
        #pragma unroll
        for (int e = 0; e < EE; e++) p[e] += xv * gw[e * DD + d];
    }
    #pragma unroll
    for (int e = 0; e < EE; e++) sh[e * 256 + t] = p[e];
    __syncthreads();
    for (int o = 128; o > 0; o >>= 1) {
        if (t < o) {
            #pragma unroll
            for (int e = 0; e < EE; e++) sh[e * 256 + t] += sh[e * 256 + t + o];
        }
        __syncthreads();
    }
    if (t == 0) {
        float lg[EE];
        float mx = -1e30f;
        #pragma unroll
        for (int e = 0; e < EE; e++) { lg[e] = sh[e * 256] + gb[e]; mx = fmaxf(mx, lg[e]); }
        float sum = 0.f;
        #pragma unroll
        for (int e = 0; e < EE; e++) { lg[e] = expf(lg[e] - mx); sum += lg[e]; }
        float invs = 1.f / sum;
        #pragma unroll
        for (int e = 0; e < EE; e++) lg[e] *= invs;
        int i0 = 0;
        #pragma unroll
        for (int e = 1; e < EE; e++) if (lg[e] > lg[i0]) i0 = e;
        int i1 = (i0 == 0) ? 1 : 0;
        #pragma unroll
        for (int e = 0; e < EE; e++) if (e != i0 && lg[e] > lg[i1]) i1 = e;
        float w0 = lg[i0], w1 = lg[i1];
        float ws = 1.f / (w0 + w1);
        topi[2 * s]     = i0;
        topi[2 * s + 1] = i1;
        topw[2 * s]     = w0 * ws;
        topw[2 * s + 1] = w1 * ws;
    }
}

// ---------------- capacity routing: parallel block scan per expert ----------------
__global__ void route_kernel(const int* __restrict__ topi, const float* __restrict__ topw,
                             int* __restrict__ slot, float* __restrict__ slotw)
{
    __shared__ int cnt[256];
    int e = blockIdx.x;
    int t = threadIdx.x;
    int base = t * 8;
    int loc[8]; float lw[8]; int c = 0;
    #pragma unroll
    for (int i = 0; i < 8; i++) {
        int s = base + i;
        float w = -1.f;
        if (topi[2 * s] == e) w = topw[2 * s];
        else if (topi[2 * s + 1] == e) w = topw[2 * s + 1];
        if (w >= 0.f) { loc[c] = s; lw[c] = w; c++; }
    }
    cnt[t] = c;
    __syncthreads();
    for (int off = 1; off < 256; off <<= 1) {
        int v = 0;
        if (t >= off) v = cnt[t - off];
        __syncthreads();
        cnt[t] += v;
        __syncthreads();
    }
    int start = cnt[t] - c;
    for (int i = 0; i < c; i++) {
        int pos = start + i;
        if (pos < CAP) {
            slot[e * CAP + pos]  = loc[i];
            slotw[e * CAP + pos] = lw[i];
        }
    }
    int total = cnt[255];
    __syncthreads();
    for (int p = total + t; p < CAP; p += 256) {
        slot[e * CAP + p]  = -1;
        slotw[e * CAP + p] = 0.f;
    }
}

__global__ void gather_xe(const float* __restrict__ x, const int* __restrict__ slot,
                          float* __restrict__ xe)
{
    int sl = blockIdx.x;
    int t = slot[sl];
    float* dst = xe + (long)sl * DD;
    if (t < 0) {
        for (int d = threadIdx.x; d < DD; d += 256) dst[d] = 0.f;
    } else {
        const float* srcp = x + (long)t * DD;
        for (int d = threadIdx.x; d < DD; d += 256) dst[d] = srcp[d];
    }
}

__global__ void scatter_oe(const float* __restrict__ oe, const int* __restrict__ slot,
                           const float* __restrict__ slotw, float* __restrict__ y)
{
    int sl = blockIdx.x;
    int t = slot[sl];
    if (t < 0) return;
    float w = slotw[sl];
    const float* srcp = oe + (long)sl * DD;
    float* dst = y + (long)t * DD;
    for (int d = threadIdx.x; d < DD; d += 256) atomicAdd(&dst[d], srcp[d] * w);
}

// ---------------- host launcher ----------------
extern "C" void kernel_launch(void* const* d_in, const int* in_sizes, int n_in,
                              void* d_out, int out_size)
{
    const int*   src        = (const int*)  d_in[0];
    const float* emb        = (const float*)d_in[1];
    const float* in_proj_w  = (const float*)d_in[2];
    const float* in_proj_b  = (const float*)d_in[3];
    const float* out_proj_w = (const float*)d_in[4];
    const float* out_proj_b = (const float*)d_in[5];
    const float* ln1_w      = (const float*)d_in[6];
    const float* ln1_b      = (const float*)d_in[7];
    const float* ln2_w      = (const float*)d_in[8];
    const float* ln2_b      = (const float*)d_in[9];
    const float* gate_w     = (const float*)d_in[10];
    const float* gate_b     = (const float*)d_in[11];
    const float* w1         = (const float*)d_in[12];
    const float* b1         = (const float*)d_in[13];
    const float* w2         = (const float*)d_in[14];
    const float* b2         = (const float*)d_in[15];
    const float* dec_w      = (const float*)d_in[16];
    const float* dec_b      = (const float*)d_in[17];
    float* out = (float*)d_out;

    float *x, *qkv, *q, *k, *vt, *av, *sc, *attn, *tmp, *xe, *hbuf, *oe, *topw, *slotw;
    int *topi, *slot;
    cudaGetSymbolAddress((void**)&x,    g_x);
    cudaGetSymbolAddress((void**)&qkv,  g_qkv);
    cudaGetSymbolAddress((void**)&q,    g_q);
    cudaGetSymbolAddress((void**)&k,    g_k);
    cudaGetSymbolAddress((void**)&vt,   g_vt);
    cudaGetSymbolAddress((void**)&av,   g_av);
    cudaGetSymbolAddress((void**)&sc,   g_sc);
    cudaGetSymbolAddress((void**)&attn, g_attn);
    cudaGetSymbolAddress((void**)&tmp,  g_tmp);
    cudaGetSymbolAddress((void**)&xe,   g_xe);
    cudaGetSymbolAddress((void**)&hbuf, g_hbuf);
    cudaGetSymbolAddress((void**)&oe,   g_oe);
    cudaGetSymbolAddress((void**)&topi, g_topi);
    cudaGetSymbolAddress((void**)&topw, g_topw);
    cudaGetSymbolAddress((void**)&slot, g_slot);
    cudaGetSymbolAddress((void**)&slotw, g_slotw);

    embed_kernel<<<(SS * DD) / 256, 256>>>(src, emb, x);

    for (int l = 0; l < NLAYER; l++) {
        const float* wi = in_proj_w  + (long)l * D3 * DD;
        const float* bi = in_proj_b  + (long)l * D3;
        const float* wo = out_proj_w + (long)l * DD * DD;
        const float* bo = out_proj_b + (long)l * DD;
        const float* gw = gate_w     + (long)l * EE * DD;
        const float* gb = gate_b     + (long)l * EE;
        const float* w1l = w1        + (long)l * EE * FF * DD;
        const float* b1l = b1        + (long)l * EE * FF;
        const float* w2l = w2        + (long)l * EE * DD * FF;
        const float* b2l = b2        + (long)l * EE * DD;

        // qkv = x @ wi^T + bi   [2048 x 3072], K=1024
        gemm_tc<<<dim3(SS/GBM, D3/GBN, 1), 256>>>(x, wi, bi, qkv,
            SS, D3, DD, DD, DD, D3, 0, 0, 0, 0, 1.f, 0, 0);

        split_heads<<<(SS * DD) / 256, 256>>>(qkv, q, k, vt);

        // scores = q @ k^T / 8   batch=64, M=N=512, K=64, causal block skip
        gemm_tc<<<dim3(LL/GBM, LL/GBN, BB*HH), 256>>>(q, k, nullptr, sc,
            LL, LL, HD, HD, HD, LL,
            (long)LL*HD, (long)LL*HD, (long)LL*LL, 0, 0.125f, 0, 1);

        softmax_causal<<<BB * HH * LL, 128>>>(sc);

        // av = attn @ vt^T   batch=64, M=512, N=64, K=512
        gemm_tc<<<dim3(LL/GBM, 1, BB*HH), 256>>>(sc, vt, nullptr, av,
            LL, HD, LL, LL, LL, HD,
            (long)LL*LL, (long)HD*LL, (long)LL*HD, 0, 1.f, 0, 0);

        merge_heads<<<(SS * DD) / 256, 256>>>(av, attn);

        // proj = attn @ wo^T + bo   [2048 x 1024], K=1024
        gemm_tc<<<dim3(SS/GBM, DD/GBN, 1), 256>>>(attn, wo, bo, tmp,
            SS, DD, DD, DD, DD, DD, 0, 0, 0, 0, 1.f, 0, 0);

        add_ln<<<SS, 256>>>(x, tmp, ln1_w + l * DD, ln1_b + l * DD, x);

        // ---- MoE ----
        gate_topk<<<SS, 256>>>(x, gw, gb, topi, topw);
        route_kernel<<<EE, 256>>>(topi, topw, slot, slotw);
        gather_xe<<<EE * CAP, 256>>>(x, slot, xe);

        // h = relu(xe @ w1^T + b1)   batch=8, M=320, N=4096, K=1024
        gemm_tc<<<dim3((CAP+GBM-1)/GBM, FF/GBN, EE), 256>>>(xe, w1l, b1l, hbuf,
            CAP, FF, DD, DD, DD, FF,
            (long)CAP*DD, (long)FF*DD, (long)CAP*FF, FF, 1.f, 1, 0);

        // oe = h @ w2^T + b2   batch=8, M=320, N=1024, K=4096
        gemm_tc<<<dim3((CAP+GBM-1)/GBM, DD/GBN, EE), 256>>>(hbuf, w2l, b2l, oe,
            CAP, DD, FF, FF, FF, DD,
            (long)CAP*FF, (long)DD*FF, (long)CAP*DD, DD, 1.f, 0, 0);

        cudaMemsetAsync(tmp, 0, (size_t)SS * DD * sizeof(float), 0);
        scatter_oe<<<EE * CAP, 256>>>(oe, slot, slotw, tmp);

        add_ln<<<SS, 256>>>(x, tmp, ln2_w + l * DD, ln2_b + l * DD, x);
    }

    // logits = x @ dec_w^T + dec_b   [2048 x 32000], K=1024
    gemm_tc<<<dim3(SS/GBM, (VV+GBN-1)/GBN, 1), 256>>>(x, dec_w, dec_b, out,
        SS, VV, DD, DD, DD, VV, 0, 0, 0, 0, 1.f, 0, 0);
}

// round 6
// speedup vs baseline: 2.2257x; 1.0875x over previous
#include <cuda_runtime.h>
#include <cuda_bf16.h>
#include <math.h>

// ---------------- problem constants ----------------
#define BB 4
#define LL 512
#define VV 32000
#define DD 1024
#define HH 16
#define HD 64
#define NLAYER 2
#define EE 8
#define KK 2
#define FF 4096
#define SS (BB*LL)      // 2048
#define CAP 320
#define D3 (3*DD)       // 3072

// ---------------- static scratch ----------------
__device__ float g_x[SS*DD];
__device__ float g_qkv[SS*D3];
__device__ float g_q[SS*DD];
__device__ float g_k[SS*DD];
__device__ float g_vt[SS*DD];           // V transposed per head: [(b,h), d, l]
__device__ float g_av[SS*DD];
__device__ float g_sc[BB*HH*LL*LL];     // 64 MB
__device__ float g_attn[SS*DD];
__device__ float g_tmp[SS*DD];
__device__ float g_xe[EE*CAP*DD];
__device__ float g_hbuf[EE*CAP*FF];
__device__ float g_oe[EE*CAP*DD];
__device__ int   g_topi[SS*2];
__device__ float g_topw[SS*2];
__device__ int   g_slot[EE*CAP];
__device__ float g_slotw[EE*CAP];

// ---------------- reductions ----------------
__device__ __forceinline__ float blockReduceSum(float v){
    __shared__ float sh[32];
    int lane = threadIdx.x & 31, wid = threadIdx.x >> 5;
    int nw = (blockDim.x + 31) >> 5;
    #pragma unroll
    for (int o = 16; o > 0; o >>= 1) v += __shfl_down_sync(0xffffffffu, v, o);
    __syncthreads();
    if (lane == 0) sh[wid] = v;
    __syncthreads();
    if (wid == 0) {
        v = (lane < nw) ? sh[lane] : 0.f;
        #pragma unroll
        for (int o = 16; o > 0; o >>= 1) v += __shfl_down_sync(0xffffffffu, v, o);
        if (lane == 0) sh[0] = v;
    }
    __syncthreads();
    return sh[0];
}

__device__ __forceinline__ float blockReduceMax(float v){
    __shared__ float sh[32];
    int lane = threadIdx.x & 31, wid = threadIdx.x >> 5;
    int nw = (blockDim.x + 31) >> 5;
    #pragma unroll
    for (int o = 16; o > 0; o >>= 1) v = fmaxf(v, __shfl_down_sync(0xffffffffu, v, o));
    __syncthreads();
    if (lane == 0) sh[wid] = v;
    __syncthreads();
    if (wid == 0) {
        v = (lane < nw) ? sh[lane] : -1e30f;
        #pragma unroll
        for (int o = 16; o > 0; o >>= 1) v = fmaxf(v, __shfl_down_sync(0xffffffffu, v, o));
        if (lane == 0) sh[0] = v;
    }
    __syncthreads();
    return sh[0];
}

// ============================================================
// Tensor-core GEMM, bf16x3 split on m16n8k16, cp.async pipelined:
//   C = act(alpha * A(MxK) * B(NxK)^T + bias)
// Block 128x128x32, 8 warps, warp tile 64x32.
// 2-stage cp.async staging of raw f32 tiles (zero register cost),
// split f32->bf16(hi,lo) happens smem->smem; MMAs overlap the
// in-flight cp.async of the NEXT tile.
// ============================================================
#define GBM 128
#define GBN 128
#define GBK 32
#define LDW 20    // bf16 buf row stride in 32-bit words (16 pairs + 4 pad)
#define SFL 36    // f32 stage row stride in floats (32 + 4 pad)
// f32 stage: A(128*36) + B(128*36) floats per stage, 2 stages
#define STAGE_F (2 * GBM * SFL)                 // floats per stage (A+B)
#define SMEM_F32 (2 * STAGE_F)                  // 18432 floats = 72KB
#define SMEM_BF16 (4 * GBM * LDW)               // 10240 words = 40KB
#define GEMM_SMEM_BYTES ((SMEM_F32 + SMEM_BF16) * 4)   // 114688 B

#define MMA_BF16(d, a, b) \
    asm volatile("mma.sync.aligned.m16n8k16.row.col.f32.bf16.bf16.f32 " \
        "{%0,%1,%2,%3},{%4,%5,%6,%7},{%8,%9},{%0,%1,%2,%3};" \
        : "+f"(d[0]), "+f"(d[1]), "+f"(d[2]), "+f"(d[3]) \
        : "r"(a[0]), "r"(a[1]), "r"(a[2]), "r"(a[3]), "r"(b[0]), "r"(b[1]))

__device__ __forceinline__ void splt2(float x, float y, unsigned& hi, unsigned& lo){
    __nv_bfloat162 H, L;
    H.x = __float2bfloat16_rn(x);
    H.y = __float2bfloat16_rn(y);
    L.x = __float2bfloat16_rn(x - __bfloat162float(H.x));
    L.y = __float2bfloat16_rn(y - __bfloat162float(H.y));
    hi = *(unsigned*)&H;
    lo = *(unsigned*)&L;
}

__device__ __forceinline__ void cp16(unsigned dst, const float* src, bool pred){
    asm volatile("cp.async.cg.shared.global [%0], [%1], 16, %2;"
        :: "r"(dst), "l"(src), "r"(pred ? 16 : 0));
}

__global__ void __launch_bounds__(256, 2)
gemm_tc(const float* __restrict__ A, const float* __restrict__ Bm,
        const float* __restrict__ bias, float* __restrict__ C,
        int M, int N, int K, int lda, int ldb, int ldc,
        long aStride, long bStride, long cStride, long biasStride,
        float alpha, int relu, int causal)
{
    extern __shared__ float smf[];
    unsigned* sAh = (unsigned*)(smf + SMEM_F32);
    unsigned* sAl = sAh + GBM * LDW;
    unsigned* sBh = sAl + GBM * LDW;
    unsigned* sBl = sBh + GBM * LDW;

    int m0 = blockIdx.x * GBM;
    int n0 = blockIdx.y * GBN;
    if (causal && n0 > m0 + GBM - 1) return;   // fully-masked causal block

    int z = blockIdx.z;
    A  += (long)z * aStride;
    Bm += (long)z * bStride;
    C  += (long)z * cStride;
    if (bias) bias += (long)z * biasStride;

    int tid = threadIdx.x;
    int wid = tid >> 5, lane = tid & 31;
    int wm = (wid & 1) * 64;        // warp m-origin
    int wn = (wid >> 1) * 32;       // warp n-origin

    float c[4][4][4];
    #pragma unroll
    for (int i = 0; i < 4; i++)
        #pragma unroll
        for (int j = 0; j < 4; j++)
            #pragma unroll
            for (int r = 0; r < 4; r++) c[i][j][r] = 0.f;

    int lrow = tid >> 3;           // 0..31
    int lcol = (tid & 7) * 4;      // gmem/stage k offset: 0,4,...,28
    int kp0  = (tid & 7) * 2;      // bf16 pair index: 0,2,...,14

    // per-thread row validity / clamped row indices (avoid OOB addresses)
    int gmRow[4], gnRow[4];
    bool gmOk[4], gnOk[4];
    #pragma unroll
    for (int r = 0; r < 4; r++) {
        int row = lrow + r * 32;
        int gm = m0 + row;
        gmOk[r] = gm < M; gmRow[r] = gmOk[r] ? gm : 0;
        int gn = n0 + row;
        gnOk[r] = gn < N; gnRow[r] = gnOk[r] ? gn : 0;
    }

    unsigned stBase[2];
    {
        unsigned base = (unsigned)__cvta_generic_to_shared(smf);
        stBase[0] = base;
        stBase[1] = base + STAGE_F * 4;
    }

    auto issueCp = [&](int kt, int s) {
        unsigned aBase = stBase[s];
        unsigned bBase = stBase[s] + GBM * SFL * 4;
        #pragma unroll
        for (int r = 0; r < 4; r++) {
            int row = lrow + r * 32;
            cp16(aBase + (row * SFL + lcol) * 4, A + (long)gmRow[r] * lda + kt + lcol, gmOk[r]);
            cp16(bBase + (row * SFL + lcol) * 4, Bm + (long)gnRow[r] * ldb + kt + lcol, gnOk[r]);
        }
        asm volatile("cp.async.commit_group;" ::: "memory");
    };

    int ar = lane >> 2, acl = lane & 3;

    // prologue: stage 0
    issueCp(0, 0);

    int nIter = K / GBK;
    for (int it = 0; it < nIter; it++) {
        bool more = (it + 1) < nIter;
        if (more) issueCp((it + 1) * GBK, (it + 1) & 1);

        if (more) asm volatile("cp.async.wait_group 1;" ::: "memory");
        else      asm volatile("cp.async.wait_group 0;" ::: "memory");
        __syncthreads();   // stage[it&1] arrived + previous MMA done reading bf16

        // ---- split f32 stage -> bf16 buffers ----
        {
            const float* stA = smf + (it & 1) * STAGE_F;
            const float* stB = stA + GBM * SFL;
            #pragma unroll
            for (int r = 0; r < 4; r++) {
                int row = lrow + r * 32;
                float4 va = *(const float4*)(stA + row * SFL + lcol);
                unsigned h0, l0, h1, l1;
                splt2(va.x, va.y, h0, l0);
                splt2(va.z, va.w, h1, l1);
                sAh[row * LDW + kp0]     = h0;
                sAh[row * LDW + kp0 + 1] = h1;
                sAl[row * LDW + kp0]     = l0;
                sAl[row * LDW + kp0 + 1] = l1;

                float4 vb = *(const float4*)(stB + row * SFL + lcol);
                splt2(vb.x, vb.y, h0, l0);
                splt2(vb.z, vb.w, h1, l1);
                sBh[row * LDW + kp0]     = h0;
                sBh[row * LDW + kp0 + 1] = h1;
                sBl[row * LDW + kp0]     = l0;
                sBl[row * LDW + kp0 + 1] = l1;
            }
        }
        __syncthreads();

        // ---- two k16 chunks ----
        #pragma unroll
        for (int ks = 0; ks < 2; ks++) {
            int kb = ks * 8 + acl;
            unsigned ah[4][4], al[4][4], bh[4][2], bl[4][2];
            #pragma unroll
            for (int i = 0; i < 4; i++) {
                int r0 = (wm + i * 16 + ar) * LDW;
                int r1 = r0 + 8 * LDW;
                ah[i][0] = sAh[r0 + kb];     al[i][0] = sAl[r0 + kb];
                ah[i][1] = sAh[r1 + kb];     al[i][1] = sAl[r1 + kb];
                ah[i][2] = sAh[r0 + kb + 4]; al[i][2] = sAl[r0 + kb + 4];
                ah[i][3] = sAh[r1 + kb + 4]; al[i][3] = sAl[r1 + kb + 4];
            }
            #pragma unroll
            for (int j = 0; j < 4; j++) {
                int nr = (wn + j * 8 + ar) * LDW;
                bh[j][0] = sBh[nr + kb];     bl[j][0] = sBl[nr + kb];
                bh[j][1] = sBh[nr + kb + 4]; bl[j][1] = sBl[nr + kb + 4];
            }
            #pragma unroll
            for (int i = 0; i < 4; i++)
                #pragma unroll
                for (int j = 0; j < 4; j++)
                    MMA_BF16(c[i][j], ah[i], bh[j]);
            #pragma unroll
            for (int i = 0; i < 4; i++)
                #pragma unroll
                for (int j = 0; j < 4; j++)
                    MMA_BF16(c[i][j], ah[i], bl[j]);
            #pragma unroll
            for (int i = 0; i < 4; i++)
                #pragma unroll
                for (int j = 0; j < 4; j++)
                    MMA_BF16(c[i][j], al[i], bh[j]);
        }
        // NOTE: no sync here; next iter's first sync protects bf16 bufs
    }

    // ---- epilogue ----
    int cr = lane >> 2, cc = (lane & 3) * 2;
    #pragma unroll
    for (int i = 0; i < 4; i++) {
        #pragma unroll
        for (int j = 0; j < 4; j++) {
            int gn = n0 + wn + j * 8 + cc;
            #pragma unroll
            for (int half = 0; half < 2; half++) {
                int gm = m0 + wm + i * 16 + cr + half * 8;
                if (gm >= M) continue;
                float v0 = c[i][j][half * 2 + 0] * alpha;
                float v1 = c[i][j][half * 2 + 1] * alpha;
                if (bias) {
                    if (gn < N)     v0 += bias[gn];
                    if (gn + 1 < N) v1 += bias[gn + 1];
                }
                if (relu) { v0 = fmaxf(v0, 0.f); v1 = fmaxf(v1, 0.f); }
                if (gn + 1 < N) {
                    *(float2*)(C + (long)gm * ldc + gn) = make_float2(v0, v1);
                } else if (gn < N) {
                    C[(long)gm * ldc + gn] = v0;
                }
            }
        }
    }
}

// ---------------- embedding + positional encoding ----------------
__global__ void embed_kernel(const int* __restrict__ src, const float* __restrict__ emb,
                             float* __restrict__ x)
{
    long i = (long)blockIdx.x * 256 + threadIdx.x;
    int s = (int)(i >> 10);
    int d = (int)(i & 1023);
    int l = s & (LL - 1);
    int tok = src[s];
    int half2 = (d >> 1) * 2;
    float div = __expf(-(float)half2 * (logf(10000.f) / (float)DD));
    float arg = (float)l * div;
    float pe = (d & 1) ? cosf(arg) : sinf(arg);
    x[i] = emb[(long)tok * DD + d] * 32.0f + pe;
}

// ---------------- head split (V transposed) / merge ----------------
__global__ void split_heads(const float* __restrict__ qkv,
                            float* __restrict__ q, float* __restrict__ k, float* __restrict__ vt)
{
    long i = (long)blockIdx.x * 256 + threadIdx.x;
    int s = (int)(i >> 10);
    int dc = (int)(i & 1023);
    int h = dc >> 6;
    int d = dc & 63;
    int b = s >> 9;
    int l = s & 511;
    long srcoff = (long)s * D3 + h * HD + d;
    long dst = (((long)(b * HH + h) * LL) + l) * HD + d;
    q[dst] = qkv[srcoff];
    k[dst] = qkv[srcoff + DD];
    long vdst = (((long)(b * HH + h) * HD) + d) * LL + l;
    vt[vdst] = qkv[srcoff + 2 * DD];
}

__global__ void merge_heads(const float* __restrict__ av, float* __restrict__ out)
{
    long i = (long)blockIdx.x * 256 + threadIdx.x;
    int s = (int)(i >> 10);
    int dc = (int)(i & 1023);
    int h = dc >> 6;
    int d = dc & 63;
    int b = s >> 9;
    int l = s & 511;
    long srcoff = (((long)(b * HH + h) * LL) + l) * HD + d;
    out[i] = av[srcoff];
}

// ---------------- causal softmax (in place) ----------------
__global__ void softmax_causal(float* __restrict__ sc)
{
    int row = blockIdx.x;
    int q = row & (LL - 1);
    float* s = sc + (long)row * LL;
    int t = threadIdx.x;

    float mx = -1e30f;
    for (int k = t; k <= q; k += 128) mx = fmaxf(mx, s[k]);
    mx = blockReduceMax(mx);

    float sum = 0.f;
    for (int k = t; k <= q; k += 128) {
        float e = expf(s[k] - mx);
        s[k] = e;
        sum += e;
    }
    sum = blockReduceSum(sum);
    float inv = 1.f / sum;
    for (int k = t; k <= q; k += 128) s[k] *= inv;
    for (int k = q + 1 + t; k < LL; k += 128) s[k] = 0.f;
}

// ---------------- residual + layernorm ----------------
__global__ void add_ln(const float* __restrict__ a, const float* __restrict__ b,
                       const float* __restrict__ w, const float* __restrict__ bb,
                       float* __restrict__ out)
{
    int row = blockIdx.x;
    int t = threadIdx.x;
    const float* pa = a + (long)row * DD;
    const float* pb = b + (long)row * DD;
    float v[4];
    float s = 0.f;
    #pragma unroll
    for (int i = 0; i < 4; i++) {
        int d = t + i * 256;
        v[i] = pa[d] + pb[d];
        s += v[i];
    }
    s = blockReduceSum(s);
    float mean = s * (1.f / DD);
    float qq = 0.f;
    #pragma unroll
    for (int i = 0; i < 4; i++) {
        float dd = v[i] - mean;
        qq += dd * dd;
    }
    qq = blockReduceSum(qq);
    float inv = rsqrtf(qq * (1.f / DD) + 1e-5f);
    #pragma unroll
    for (int i = 0; i < 4; i++) {
        int d = t + i * 256;
        out[(long)row * DD + d] = (v[i] - mean) * inv * w[d] + bb[d];
    }
}

// ---------------- MoE gating ----------------
__global__ void gate_topk(const float* __restrict__ x, const float* __restrict__ gw,
                          const float* __restrict__ gb,
                          int* __restrict__ topi, float* __restrict__ topw)
{
    __shared__ float sh[EE * 256];
    int s = blockIdx.x, t = threadIdx.x;
    float p[EE];
    #pragma unroll
    for (int e = 0; e < EE; e++) p[e] = 0.f;
    for (int d = t; d < DD; d += 256) {
        float xv = x[(long)s * DD + d];
        #pragma unroll
        for (int e = 0; e < EE; e++) p[e] += xv * gw[e * DD + d];
    }
    #pragma unroll
    for (int e = 0; e < EE; e++) sh[e * 256 + t] = p[e];
    __syncthreads();
    for (int o = 128; o > 0; o >>= 1) {
        if (t < o) {
            #pragma unroll
            for (int e = 0; e < EE; e++) sh[e * 256 + t] += sh[e * 256 + t + o];
        }
        __syncthreads();
    }
    if (t == 0) {
        float lg[EE];
        float mx = -1e30f;
        #pragma unroll
        for (int e = 0; e < EE; e++) { lg[e] = sh[e * 256] + gb[e]; mx = fmaxf(mx, lg[e]); }
        float sum = 0.f;
        #pragma unroll
        for (int e = 0; e < EE; e++) { lg[e] = expf(lg[e] - mx); sum += lg[e]; }
        float invs = 1.f / sum;
        #pragma unroll
        for (int e = 0; e < EE; e++) lg[e] *= invs;
        int i0 = 0;
        #pragma unroll
        for (int e = 1; e < EE; e++) if (lg[e] > lg[i0]) i0 = e;
        int i1 = (i0 == 0) ? 1 : 0;
        #pragma unroll
        for (int e = 0; e < EE; e++) if (e != i0 && lg[e] > lg[i1]) i1 = e;
        float w0 = lg[i0], w1 = lg[i1];
        float ws = 1.f / (w0 + w1);
        topi[2 * s]     = i0;
        topi[2 * s + 1] = i1;
        topw[2 * s]     = w0 * ws;
        topw[2 * s + 1] = w1 * ws;
    }
}

// ---------------- capacity routing: parallel block scan per expert ----------------
__global__ void route_kernel(const int* __restrict__ topi, const float* __restrict__ topw,
                             int* __restrict__ slot, float* __restrict__ slotw)
{
    __shared__ int cnt[256];
    int e = blockIdx.x;
    int t = threadIdx.x;
    int base = t * 8;
    int loc[8]; float lw[8]; int c = 0;
    #pragma unroll
    for (int i = 0; i < 8; i++) {
        int s = base + i;
        float w = -1.f;
        if (topi[2 * s] == e) w = topw[2 * s];
        else if (topi[2 * s + 1] == e) w = topw[2 * s + 1];
        if (w >= 0.f) { loc[c] = s; lw[c] = w; c++; }
    }
    cnt[t] = c;
    __syncthreads();
    for (int off = 1; off < 256; off <<= 1) {
        int v = 0;
        if (t >= off) v = cnt[t - off];
        __syncthreads();
        cnt[t] += v;
        __syncthreads();
    }
    int start = cnt[t] - c;
    for (int i = 0; i < c; i++) {
        int pos = start + i;
        if (pos < CAP) {
            slot[e * CAP + pos]  = loc[i];
            slotw[e * CAP + pos] = lw[i];
        }
    }
    int total = cnt[255];
    __syncthreads();
    for (int p = total + t; p < CAP; p += 256) {
        slot[e * CAP + p]  = -1;
        slotw[e * CAP + p] = 0.f;
    }
}

__global__ void gather_xe(const float* __restrict__ x, const int* __restrict__ slot,
                          float* __restrict__ xe)
{
    int sl = blockIdx.x;
    int t = slot[sl];
    float* dst = xe + (long)sl * DD;
    if (t < 0) {
        for (int d = threadIdx.x; d < DD; d += 256) dst[d] = 0.f;
    } else {
        const float* srcp = x + (long)t * DD;
        for (int d = threadIdx.x; d < DD; d += 256) dst[d] = srcp[d];
    }
}

__global__ void scatter_oe(const float* __restrict__ oe, const int* __restrict__ slot,
                           const float* __restrict__ slotw, float* __restrict__ y)
{
    int sl = blockIdx.x;
    int t = slot[sl];
    if (t < 0) return;
    float w = slotw[sl];
    const float* srcp = oe + (long)sl * DD;
    float* dst = y + (long)t * DD;
    for (int d = threadIdx.x; d < DD; d += 256) atomicAdd(&dst[d], srcp[d] * w);
}

// ---------------- host launcher ----------------
extern "C" void kernel_launch(void* const* d_in, const int* in_sizes, int n_in,
                              void* d_out, int out_size)
{
    const int*   src        = (const int*)  d_in[0];
    const float* emb        = (const float*)d_in[1];
    const float* in_proj_w  = (const float*)d_in[2];
    const float* in_proj_b  = (const float*)d_in[3];
    const float* out_proj_w = (const float*)d_in[4];
    const float* out_proj_b = (const float*)d_in[5];
    const float* ln1_w      = (const float*)d_in[6];
    const float* ln1_b      = (const float*)d_in[7];
    const float* ln2_w      = (const float*)d_in[8];
    const float* ln2_b      = (const float*)d_in[9];
    const float* gate_w     = (const float*)d_in[10];
    const float* gate_b     = (const float*)d_in[11];
    const float* w1         = (const float*)d_in[12];
    const float* b1         = (const float*)d_in[13];
    const float* w2         = (const float*)d_in[14];
    const float* b2         = (const float*)d_in[15];
    const float* dec_w      = (const float*)d_in[16];
    const float* dec_b      = (const float*)d_in[17];
    float* out = (float*)d_out;

    static int smem_set = 0;
    if (!smem_set) {
        cudaFuncSetAttribute(gemm_tc, cudaFuncAttributeMaxDynamicSharedMemorySize, GEMM_SMEM_BYTES);
        smem_set = 1;
    }

    float *x, *qkv, *q, *k, *vt, *av, *sc, *attn, *tmp, *xe, *hbuf, *oe, *topw, *slotw;
    int *topi, *slot;
    cudaGetSymbolAddress((void**)&x,    g_x);
    cudaGetSymbolAddress((void**)&qkv,  g_qkv);
    cudaGetSymbolAddress((void**)&q,    g_q);
    cudaGetSymbolAddress((void**)&k,    g_k);
    cudaGetSymbolAddress((void**)&vt,   g_vt);
    cudaGetSymbolAddress((void**)&av,   g_av);
    cudaGetSymbolAddress((void**)&sc,   g_sc);
    cudaGetSymbolAddress((void**)&attn, g_attn);
    cudaGetSymbolAddress((void**)&tmp,  g_tmp);
    cudaGetSymbolAddress((void**)&xe,   g_xe);
    cudaGetSymbolAddress((void**)&hbuf, g_hbuf);
    cudaGetSymbolAddress((void**)&oe,   g_oe);
    cudaGetSymbolAddress((void**)&topi, g_topi);
    cudaGetSymbolAddress((void**)&topw, g_topw);
    cudaGetSymbolAddress((void**)&slot, g_slot);
    cudaGetSymbolAddress((void**)&slotw, g_slotw);

    embed_kernel<<<(SS * DD) / 256, 256>>>(src, emb, x);

    for (int l = 0; l < NLAYER; l++) {
        const float* wi = in_proj_w  + (long)l * D3 * DD;
        const float* bi = in_proj_b  + (long)l * D3;
        const float* wo = out_proj_w + (long)l * DD * DD;
        const float* bo = out_proj_b + (long)l * DD;
        const float* gw = gate_w     + (long)l * EE * DD;
        const float* gb = gate_b     + (long)l * EE;
        const float* w1l = w1        + (long)l * EE * FF * DD;
        const float* b1l = b1        + (long)l * EE * FF;
        const float* w2l = w2        + (long)l * EE * DD * FF;
        const float* b2l = b2        + (long)l * EE * DD;

        // qkv = x @ wi^T + bi   [2048 x 3072], K=1024
        gemm_tc<<<dim3(SS/GBM, D3/GBN, 1), 256, GEMM_SMEM_BYTES>>>(x, wi, bi, qkv,
            SS, D3, DD, DD, DD, D3, 0, 0, 0, 0, 1.f, 0, 0);

        split_heads<<<(SS * DD) / 256, 256>>>(qkv, q, k, vt);

        // scores = q @ k^T / 8   batch=64, M=N=512, K=64, causal block skip
        gemm_tc<<<dim3(LL/GBM, LL/GBN, BB*HH), 256, GEMM_SMEM_BYTES>>>(q, k, nullptr, sc,
            LL, LL, HD, HD, HD, LL,
            (long)LL*HD, (long)LL*HD, (long)LL*LL, 0, 0.125f, 0, 1);

        softmax_causal<<<BB * HH * LL, 128>>>(sc);

        // av = attn @ vt^T   batch=64, M=512, N=64, K=512
        gemm_tc<<<dim3(LL/GBM, 1, BB*HH), 256, GEMM_SMEM_BYTES>>>(sc, vt, nullptr, av,
            LL, HD, LL, LL, LL, HD,
            (long)LL*LL, (long)HD*LL, (long)LL*HD, 0, 1.f, 0, 0);

        merge_heads<<<(SS * DD) / 256, 256>>>(av, attn);

        // proj = attn @ wo^T + bo   [2048 x 1024], K=1024
        gemm_tc<<<dim3(SS/GBM, DD/GBN, 1), 256, GEMM_SMEM_BYTES>>>(attn, wo, bo, tmp,
            SS, DD, DD, DD, DD, DD, 0, 0, 0, 0, 1.f, 0, 0);

        add_ln<<<SS, 256>>>(x, tmp, ln1_w + l * DD, ln1_b + l * DD, x);

        // ---- MoE ----
        gate_topk<<<SS, 256>>>(x, gw, gb, topi, topw);
        route_kernel<<<EE, 256>>>(topi, topw, slot, slotw);
        gather_xe<<<EE * CAP, 256>>>(x, slot, xe);

        // h = relu(xe @ w1^T + b1)   batch=8, M=320, N=4096, K=1024
        gemm_tc<<<dim3((CAP+GBM-1)/GBM, FF/GBN, EE), 256, GEMM_SMEM_BYTES>>>(xe, w1l, b1l, hbuf,
            CAP, FF, DD, DD, DD, FF,
            (long)CAP*DD, (long)FF*DD, (long)CAP*FF, FF, 1.f, 1, 0);

        // oe = h @ w2^T + b2   batch=8, M=320, N=1024, K=4096
        gemm_tc<<<dim3((CAP+GBM-1)/GBM, DD/GBN, EE), 256, GEMM_SMEM_BYTES>>>(hbuf, w2l, b2l, oe,
            CAP, DD, FF, FF, FF, DD,
            (long)CAP*FF, (long)DD*FF, (long)CAP*DD, DD, 1.f, 0, 0);

        cudaMemsetAsync(tmp, 0, (size_t)SS * DD * sizeof(float), 0);
        scatter_oe<<<EE * CAP, 256>>>(oe, slot, slotw, tmp);

        add_ln<<<SS, 256>>>(x, tmp, ln2_w + l * DD, ln2_b + l * DD, x);
    }

    // logits = x @ dec_w^T + dec_b   [2048 x 32000], K=1024
    gemm_tc<<<dim3(SS/GBM, (VV+GBN-1)/GBN, 1), 256, GEMM_SMEM_BYTES>>>(x, dec_w, dec_b, out,
        SS, VV, DD, DD, DD, VV, 0, 0, 0, 0, 1.f, 0, 0);
}

// round 8
// speedup vs baseline: 2.4545x; 1.1028x over previous
#include <cuda_runtime.h>
#include <cuda_bf16.h>
#include <math.h>

// ---------------- problem constants ----------------
#define BB 4
#define LL 512
#define VV 32000
#define DD 1024
#define HH 16
#define HD 64
#define NLAYER 2
#define EE 8
#define KK 2
#define FF 4096
#define SS (BB*LL)      // 2048
#define CAP 320
#define D3 (3*DD)       // 3072

// ---------------- static scratch ----------------
__device__ float g_x[SS*DD];
__device__ float g_qkv[SS*D3];
__device__ float g_q[SS*DD];
__device__ float g_k[SS*DD];
__device__ float g_vt[SS*DD];           // V transposed per head: [(b,h), d, l]
__device__ float g_av[SS*DD];
__device__ float g_sc[BB*HH*LL*LL];     // 64 MB
__device__ float g_attn[SS*DD];
__device__ float g_tmp[SS*DD];
__device__ float g_xe[EE*CAP*DD];
__device__ float g_hbuf[EE*CAP*FF];
__device__ float g_oe[EE*CAP*DD];
__device__ int   g_topi[SS*2];
__device__ float g_topw[SS*2];
__device__ int   g_slot[EE*CAP];
__device__ float g_slotw[EE*CAP];

// ---------------- reductions ----------------
__device__ __forceinline__ float blockReduceSum(float v){
    __shared__ float sh[32];
    int lane = threadIdx.x & 31, wid = threadIdx.x >> 5;
    int nw = (blockDim.x + 31) >> 5;
    #pragma unroll
    for (int o = 16; o > 0; o >>= 1) v += __shfl_down_sync(0xffffffffu, v, o);
    __syncthreads();
    if (lane == 0) sh[wid] = v;
    __syncthreads();
    if (wid == 0) {
        v = (lane < nw) ? sh[lane] : 0.f;
        #pragma unroll
        for (int o = 16; o > 0; o >>= 1) v += __shfl_down_sync(0xffffffffu, v, o);
        if (lane == 0) sh[0] = v;
    }
    __syncthreads();
    return sh[0];
}

__device__ __forceinline__ float blockReduceMax(float v){
    __shared__ float sh[32];
    int lane = threadIdx.x & 31, wid = threadIdx.x >> 5;
    int nw = (blockDim.x + 31) >> 5;
    #pragma unroll
    for (int o = 16; o > 0; o >>= 1) v = fmaxf(v, __shfl_down_sync(0xffffffffu, v, o));
    __syncthreads();
    if (lane == 0) sh[wid] = v;
    __syncthreads();
    if (wid == 0) {
        v = (lane < nw) ? sh[lane] : -1e30f;
        #pragma unroll
        for (int o = 16; o > 0; o >>= 1) v = fmaxf(v, __shfl_down_sync(0xffffffffu, v, o));
        if (lane == 0) sh[0] = v;
    }
    __syncthreads();
    return sh[0];
}

// ============================================================
// Tensor-core GEMM, bf16x3 split on m16n8k16, cp.async + ldmatrix:
//   C = act(alpha * A(MxK) * B(NxK)^T + bias)
// Block 128x128x32, 8 warps, warp tile 64x32.
// Fragments loaded with ldmatrix.x4 (12 per ks-chunk instead of
// 48 scalar LDS). k16-chunk offset = ks*8 WORDS (fixed R7 bug).
// ============================================================
#define GBM 128
#define GBN 128
#define GBK 32
#define LDW 20    // bf16 buf row stride in 32-bit words (16 pairs + 4 pad)
#define SFL 36    // f32 stage row stride in floats (32 + 4 pad)
#define STAGE_F (2 * GBM * SFL)                 // floats per stage (A+B)
#define SMEM_F32 (2 * STAGE_F)                  // 72KB
#define SMEM_BF16 (4 * GBM * LDW)               // 40KB
#define GEMM_SMEM_BYTES ((SMEM_F32 + SMEM_BF16) * 4)   // 114688 B

#define MMA_BF16(d, a, b) \
    asm volatile("mma.sync.aligned.m16n8k16.row.col.f32.bf16.bf16.f32 " \
        "{%0,%1,%2,%3},{%4,%5,%6,%7},{%8,%9},{%0,%1,%2,%3};" \
        : "+f"(d[0]), "+f"(d[1]), "+f"(d[2]), "+f"(d[3]) \
        : "r"(a[0]), "r"(a[1]), "r"(a[2]), "r"(a[3]), "r"(b[0]), "r"(b[1]))

#define LDSM4(r0, r1, r2, r3, addr) \
    asm volatile("ldmatrix.sync.aligned.m8n8.x4.shared.b16 {%0,%1,%2,%3}, [%4];" \
        : "=r"(r0), "=r"(r1), "=r"(r2), "=r"(r3) : "r"(addr))

__device__ __forceinline__ void splt2(float x, float y, unsigned& hi, unsigned& lo){
    __nv_bfloat162 H, L;
    H.x = __float2bfloat16_rn(x);
    H.y = __float2bfloat16_rn(y);
    L.x = __float2bfloat16_rn(x - __bfloat162float(H.x));
    L.y = __float2bfloat16_rn(y - __bfloat162float(H.y));
    hi = *(unsigned*)&H;
    lo = *(unsigned*)&L;
}

__device__ __forceinline__ void cp16(unsigned dst, const float* src, bool pred){
    asm volatile("cp.async.cg.shared.global [%0], [%1], 16, %2;"
        :: "r"(dst), "l"(src), "r"(pred ? 16 : 0));
}

__global__ void __launch_bounds__(256, 2)
gemm_tc(const float* __restrict__ A, const float* __restrict__ Bm,
        const float* __restrict__ bias, float* __restrict__ C,
        int M, int N, int K, int lda, int ldb, int ldc,
        long aStride, long bStride, long cStride, long biasStride,
        float alpha, int relu, int causal)
{
    extern __shared__ float smf[];
    unsigned* sAh = (unsigned*)(smf + SMEM_F32);
    unsigned* sAl = sAh + GBM * LDW;
    unsigned* sBh = sAl + GBM * LDW;
    unsigned* sBl = sBh + GBM * LDW;

    int m0 = blockIdx.x * GBM;
    int n0 = blockIdx.y * GBN;
    if (causal && n0 > m0 + GBM - 1) return;   // fully-masked causal block

    int z = blockIdx.z;
    A  += (long)z * aStride;
    Bm += (long)z * bStride;
    C  += (long)z * cStride;
    if (bias) bias += (long)z * biasStride;

    int tid = threadIdx.x;
    int wid = tid >> 5, lane = tid & 31;
    int wm = (wid & 1) * 64;        // warp m-origin
    int wn = (wid >> 1) * 32;       // warp n-origin

    float c[4][4][4];
    #pragma unroll
    for (int i = 0; i < 4; i++)
        #pragma unroll
        for (int j = 0; j < 4; j++)
            #pragma unroll
            for (int r = 0; r < 4; r++) c[i][j][r] = 0.f;

    int lrow = tid >> 3;           // 0..31
    int lcol = (tid & 7) * 4;      // gmem/stage k offset: 0,4,...,28
    int kp0  = (tid & 7) * 2;      // bf16 pair index: 0,2,...,14

    int gmRow[4], gnRow[4];
    bool gmOk[4], gnOk[4];
    #pragma unroll
    for (int r = 0; r < 4; r++) {
        int row = lrow + r * 32;
        int gm = m0 + row;
        gmOk[r] = gm < M; gmRow[r] = gmOk[r] ? gm : 0;
        int gn = n0 + row;
        gnOk[r] = gn < N; gnRow[r] = gnOk[r] ? gn : 0;
    }

    unsigned smem_base = (unsigned)__cvta_generic_to_shared(smf);
    unsigned stBase[2] = { smem_base, smem_base + STAGE_F * 4 };
    unsigned sAh_s = smem_base + SMEM_F32 * 4;
    unsigned sAl_s = sAh_s + GBM * LDW * 4;
    unsigned sBh_s = sAl_s + GBM * LDW * 4;
    unsigned sBl_s = sBh_s + GBM * LDW * 4;

    // ldmatrix per-thread offsets (in words)
    // A x4: t0-15 -> rows 0-15 (k words +0); t16-31 -> rows 0-15 (k words +4)
    int aoff = (lane & 15) * LDW + ((lane >> 4) << 2);
    // B x4 (2 j-tiles): t0-7 rows0-7 k0 | t8-15 rows0-7 k+4 | t16-23 rows8-15 k0 | t24-31 rows8-15 k+4
    int boff = ((lane & 7) + ((lane >> 4) & 1) * 8) * LDW + ((lane >> 3) & 1) * 4;

    auto issueCp = [&](int kt, int s) {
        unsigned aBase = stBase[s];
        unsigned bBase = stBase[s] + GBM * SFL * 4;
        #pragma unroll
        for (int r = 0; r < 4; r++) {
            int row = lrow + r * 32;
            cp16(aBase + (row * SFL + lcol) * 4, A + (long)gmRow[r] * lda + kt + lcol, gmOk[r]);
            cp16(bBase + (row * SFL + lcol) * 4, Bm + (long)gnRow[r] * ldb + kt + lcol, gnOk[r]);
        }
        asm volatile("cp.async.commit_group;" ::: "memory");
    };

    // prologue: stage 0
    issueCp(0, 0);

    int nIter = K / GBK;
    for (int it = 0; it < nIter; it++) {
        bool more = (it + 1) < nIter;
        if (more) issueCp((it + 1) * GBK, (it + 1) & 1);

        if (more) asm volatile("cp.async.wait_group 1;" ::: "memory");
        else      asm volatile("cp.async.wait_group 0;" ::: "memory");
        __syncthreads();

        // ---- split f32 stage -> bf16 buffers ----
        {
            const float* stA = smf + (it & 1) * STAGE_F;
            const float* stB = stA + GBM * SFL;
            #pragma unroll
            for (int r = 0; r < 4; r++) {
                int row = lrow + r * 32;
                float4 va = *(const float4*)(stA + row * SFL + lcol);
                unsigned h0, l0, h1, l1;
                splt2(va.x, va.y, h0, l0);
                splt2(va.z, va.w, h1, l1);
                sAh[row * LDW + kp0]     = h0;
                sAh[row * LDW + kp0 + 1] = h1;
                sAl[row * LDW + kp0]     = l0;
                sAl[row * LDW + kp0 + 1] = l1;

                float4 vb = *(const float4*)(stB + row * SFL + lcol);
                splt2(vb.x, vb.y, h0, l0);
                splt2(vb.z, vb.w, h1, l1);
                sBh[row * LDW + kp0]     = h0;
                sBh[row * LDW + kp0 + 1] = h1;
                sBl[row * LDW + kp0]     = l0;
                sBl[row * LDW + kp0 + 1] = l1;
            }
        }
        __syncthreads();

        // ---- two k16 chunks, fragments via ldmatrix ----
        #pragma unroll
        for (int ks = 0; ks < 2; ks++) {
            int kw = ks * 8;   // word offset of this k16 chunk (16 bf16 = 8 words)
            unsigned ah[4][4], al[4][4], bh[4][2], bl[4][2];
            #pragma unroll
            for (int i = 0; i < 4; i++) {
                unsigned off = ((wm + i * 16) * LDW + aoff + kw) * 4;
                LDSM4(ah[i][0], ah[i][1], ah[i][2], ah[i][3], sAh_s + off);
                LDSM4(al[i][0], al[i][1], al[i][2], al[i][3], sAl_s + off);
            }
            #pragma unroll
            for (int p = 0; p < 2; p++) {
                unsigned off = ((wn + p * 16) * LDW + boff + kw) * 4;
                LDSM4(bh[p*2][0], bh[p*2][1], bh[p*2+1][0], bh[p*2+1][1], sBh_s + off);
                LDSM4(bl[p*2][0], bl[p*2][1], bl[p*2+1][0], bl[p*2+1][1], sBl_s + off);
            }
            #pragma unroll
            for (int i = 0; i < 4; i++)
                #pragma unroll
                for (int j = 0; j < 4; j++)
                    MMA_BF16(c[i][j], ah[i], bh[j]);
            #pragma unroll
            for (int i = 0; i < 4; i++)
                #pragma unroll
                for (int j = 0; j < 4; j++)
                    MMA_BF16(c[i][j], ah[i], bl[j]);
            #pragma unroll
            for (int i = 0; i < 4; i++)
                #pragma unroll
                for (int j = 0; j < 4; j++)
                    MMA_BF16(c[i][j], al[i], bh[j]);
        }
    }

    // ---- epilogue ----
    int cr = lane >> 2, cc = (lane & 3) * 2;
    #pragma unroll
    for (int i = 0; i < 4; i++) {
        #pragma unroll
        for (int j = 0; j < 4; j++) {
            int gn = n0 + wn + j * 8 + cc;
            #pragma unroll
            for (int half = 0; half < 2; half++) {
                int gm = m0 + wm + i * 16 + cr + half * 8;
                if (gm >= M) continue;
                float v0 = c[i][j][half * 2 + 0] * alpha;
                float v1 = c[i][j][half * 2 + 1] * alpha;
                if (bias) {
                    if (gn < N)     v0 += bias[gn];
                    if (gn + 1 < N) v1 += bias[gn + 1];
                }
                if (relu) { v0 = fmaxf(v0, 0.f); v1 = fmaxf(v1, 0.f); }
                if (gn + 1 < N) {
                    *(float2*)(C + (long)gm * ldc + gn) = make_float2(v0, v1);
                } else if (gn < N) {
                    C[(long)gm * ldc + gn] = v0;
                }
            }
        }
    }
}

// ---------------- embedding + positional encoding ----------------
__global__ void embed_kernel(const int* __restrict__ src, const float* __restrict__ emb,
                             float* __restrict__ x)
{
    long i = (long)blockIdx.x * 256 + threadIdx.x;
    int s = (int)(i >> 10);
    int d = (int)(i & 1023);
    int l = s & (LL - 1);
    int tok = src[s];
    int half2 = (d >> 1) * 2;
    float div = __expf(-(float)half2 * (logf(10000.f) / (float)DD));
    float arg = (float)l * div;
    float pe = (d & 1) ? cosf(arg) : sinf(arg);
    x[i] = emb[(long)tok * DD + d] * 32.0f + pe;
}

// ---------------- head split (V transposed) / merge ----------------
__global__ void split_heads(const float* __restrict__ qkv,
                            float* __restrict__ q, float* __restrict__ k, float* __restrict__ vt)
{
    long i = (long)blockIdx.x * 256 + threadIdx.x;
    int s = (int)(i >> 10);
    int dc = (int)(i & 1023);
    int h = dc >> 6;
    int d = dc & 63;
    int b = s >> 9;
    int l = s & 511;
    long srcoff = (long)s * D3 + h * HD + d;
    long dst = (((long)(b * HH + h) * LL) + l) * HD + d;
    q[dst] = qkv[srcoff];
    k[dst] = qkv[srcoff + DD];
    long vdst = (((long)(b * HH + h) * HD) + d) * LL + l;
    vt[vdst] = qkv[srcoff + 2 * DD];
}

__global__ void merge_heads(const float* __restrict__ av, float* __restrict__ out)
{
    long i = (long)blockIdx.x * 256 + threadIdx.x;
    int s = (int)(i >> 10);
    int dc = (int)(i & 1023);
    int h = dc >> 6;
    int d = dc & 63;
    int b = s >> 9;
    int l = s & 511;
    long srcoff = (((long)(b * HH + h) * LL) + l) * HD + d;
    out[i] = av[srcoff];
}

// ---------------- causal softmax (in place) ----------------
__global__ void softmax_causal(float* __restrict__ sc)
{
    int row = blockIdx.x;
    int q = row & (LL - 1);
    float* s = sc + (long)row * LL;
    int t = threadIdx.x;

    float mx = -1e30f;
    for (int k = t; k <= q; k += 128) mx = fmaxf(mx, s[k]);
    mx = blockReduceMax(mx);

    float sum = 0.f;
    for (int k = t; k <= q; k += 128) {
        float e = expf(s[k] - mx);
        s[k] = e;
        sum += e;
    }
    sum = blockReduceSum(sum);
    float inv = 1.f / sum;
    for (int k = t; k <= q; k += 128) s[k] *= inv;
    for (int k = q + 1 + t; k < LL; k += 128) s[k] = 0.f;
}

// ---------------- residual + layernorm ----------------
__global__ void add_ln(const float* __restrict__ a, const float* __restrict__ b,
                       const float* __restrict__ w, const float* __restrict__ bb,
                       float* __restrict__ out)
{
    int row = blockIdx.x;
    int t = threadIdx.x;
    const float* pa = a + (long)row * DD;
    const float* pb = b + (long)row * DD;
    float v[4];
    float s = 0.f;
    #pragma unroll
    for (int i = 0; i < 4; i++) {
        int d = t + i * 256;
        v[i] = pa[d] + pb[d];
        s += v[i];
    }
    s = blockReduceSum(s);
    float mean = s * (1.f / DD);
    float qq = 0.f;
    #pragma unroll
    for (int i = 0; i < 4; i++) {
        float dd = v[i] - mean;
        qq += dd * dd;
    }
    qq = blockReduceSum(qq);
    float inv = rsqrtf(qq * (1.f / DD) + 1e-5f);
    #pragma unroll
    for (int i = 0; i < 4; i++) {
        int d = t + i * 256;
        out[(long)row * DD + d] = (v[i] - mean) * inv * w[d] + bb[d];
    }
}

// ---------------- MoE gating ----------------
__global__ void gate_topk(const float* __restrict__ x, const float* __restrict__ gw,
                          const float* __restrict__ gb,
                          int* __restrict__ topi, float* __restrict__ topw)
{
    __shared__ float sh[EE * 256];
    int s = blockIdx.x, t = threadIdx.x;
    float p[EE];
    #pragma unroll
    for (int e = 0; e < EE; e++) p[e] = 0.f;
    for (int d = t; d < DD; d += 256) {
        float xv = x[(long)s * DD + d];
        #pragma unroll
        for (int e = 0; e < EE; e++) p[e] += xv * gw[e * DD + d];
    }
    #pragma unroll
    for (int e = 0; e < EE; e++) sh[e * 256 + t] = p[e];
    __syncthreads();
    for (int o = 128; o > 0; o >>= 1) {
        if (t < o) {
            #pragma unroll
            for (int e = 0; e < EE; e++) sh[e * 256 + t] += sh[e * 256 + t + o];
        }
        __syncthreads();
    }
    if (t == 0) {
        float lg[EE];
        float mx = -1e30f;
        #pragma unroll
        for (int e = 0; e < EE; e++) { lg[e] = sh[e * 256] + gb[e]; mx = fmaxf(mx, lg[e]); }
        float sum = 0.f;
        #pragma unroll
        for (int e = 0; e < EE; e++) { lg[e] = expf(lg[e] - mx); sum += lg[e]; }
        float invs = 1.f / sum;
        #pragma unroll
        for (int e = 0; e < EE; e++) lg[e] *= invs;
        int i0 = 0;
        #pragma unroll
        for (int e = 1; e < EE; e++) if (lg[e] > lg[i0]) i0 = e;
        int i1 = (i0 == 0) ? 1 : 0;
        #pragma unroll
        for (int e = 0; e < EE; e++) if (e != i0 && lg[e] > lg[i1]) i1 = e;
        float w0 = lg[i0], w1 = lg[i1];
        float ws = 1.f / (w0 + w1);
        topi[2 * s]     = i0;
        topi[2 * s + 1] = i1;
        topw[2 * s]     = w0 * ws;
        topw[2 * s + 1] = w1 * ws;
    }
}

// ---------------- capacity routing: parallel block scan per expert ----------------
__global__ void route_kernel(const int* __restrict__ topi, const float* __restrict__ topw,
                             int* __restrict__ slot, float* __restrict__ slotw)
{
    __shared__ int cnt[256];
    int e = blockIdx.x;
    int t = threadIdx.x;
    int base = t * 8;
    int loc[8]; float lw[8]; int c = 0;
    #pragma unroll
    for (int i = 0; i < 8; i++) {
        int s = base + i;
        float w = -1.f;
        if (topi[2 * s] == e) w = topw[2 * s];
        else if (topi[2 * s + 1] == e) w = topw[2 * s + 1];
        if (w >= 0.f) { loc[c] = s; lw[c] = w; c++; }
    }
    cnt[t] = c;
    __syncthreads();
    for (int off = 1; off < 256; off <<= 1) {
        int v = 0;
        if (t >= off) v = cnt[t - off];
        __syncthreads();
        cnt[t] += v;
        __syncthreads();
    }
    int start = cnt[t] - c;
    for (int i = 0; i < c; i++) {
        int pos = start + i;
        if (pos < CAP) {
            slot[e * CAP + pos]  = loc[i];
            slotw[e * CAP + pos] = lw[i];
        }
    }
    int total = cnt[255];
    __syncthreads();
    for (int p = total + t; p < CAP; p += 256) {
        slot[e * CAP + p]  = -1;
        slotw[e * CAP + p] = 0.f;
    }
}

__global__ void gather_xe(const float* __restrict__ x, const int* __restrict__ slot,
                          float* __restrict__ xe)
{
    int sl = blockIdx.x;
    int t = slot[sl];
    float* dst = xe + (long)sl * DD;
    if (t < 0) {
        for (int d = threadIdx.x; d < DD; d += 256) dst[d] = 0.f;
    } else {
        const float* srcp = x + (long)t * DD;
        for (int d = threadIdx.x; d < DD; d += 256) dst[d] = srcp[d];
    }
}

__global__ void scatter_oe(const float* __restrict__ oe, const int* __restrict__ slot,
                           const float* __restrict__ slotw, float* __restrict__ y)
{
    int sl = blockIdx.x;
    int t = slot[sl];
    if (t < 0) return;
    float w = slotw[sl];
    const float* srcp = oe + (long)sl * DD;
    float* dst = y + (long)t * DD;
    for (int d = threadIdx.x; d < DD; d += 256) atomicAdd(&dst[d], srcp[d] * w);
}

// ---------------- host launcher ----------------
extern "C" void kernel_launch(void* const* d_in, const int* in_sizes, int n_in,
                              void* d_out, int out_size)
{
    const int*   src        = (const int*)  d_in[0];
    const float* emb        = (const float*)d_in[1];
    const float* in_proj_w  = (const float*)d_in[2];
    const float* in_proj_b  = (const float*)d_in[3];
    const float* out_proj_w = (const float*)d_in[4];
    const float* out_proj_b = (const float*)d_in[5];
    const float* ln1_w      = (const float*)d_in[6];
    const float* ln1_b      = (const float*)d_in[7];
    const float* ln2_w      = (const float*)d_in[8];
    const float* ln2_b      = (const float*)d_in[9];
    const float* gate_w     = (const float*)d_in[10];
    const float* gate_b     = (const float*)d_in[11];
    const float* w1         = (const float*)d_in[12];
    const float* b1         = (const float*)d_in[13];
    const float* w2         = (const float*)d_in[14];
    const float* b2         = (const float*)d_in[15];
    const float* dec_w      = (const float*)d_in[16];
    const float* dec_b      = (const float*)d_in[17];
    float* out = (float*)d_out;

    static int smem_set = 0;
    if (!smem_set) {
        cudaFuncSetAttribute(gemm_tc, cudaFuncAttributeMaxDynamicSharedMemorySize, GEMM_SMEM_BYTES);
        smem_set = 1;
    }

    float *x, *qkv, *q, *k, *vt, *av, *sc, *attn, *tmp, *xe, *hbuf, *oe, *topw, *slotw;
    int *topi, *slot;
    cudaGetSymbolAddress((void**)&x,    g_x);
    cudaGetSymbolAddress((void**)&qkv,  g_qkv);
    cudaGetSymbolAddress((void**)&q,    g_q);
    cudaGetSymbolAddress((void**)&k,    g_k);
    cudaGetSymbolAddress((void**)&vt,   g_vt);
    cudaGetSymbolAddress((void**)&av,   g_av);
    cudaGetSymbolAddress((void**)&sc,   g_sc);
    cudaGetSymbolAddress((void**)&attn, g_attn);
    cudaGetSymbolAddress((void**)&tmp,  g_tmp);
    cudaGetSymbolAddress((void**)&xe,   g_xe);
    cudaGetSymbolAddress((void**)&hbuf, g_hbuf);
    cudaGetSymbolAddress((void**)&oe,   g_oe);
    cudaGetSymbolAddress((void**)&topi, g_topi);
    cudaGetSymbolAddress((void**)&topw, g_topw);
    cudaGetSymbolAddress((void**)&slot, g_slot);
    cudaGetSymbolAddress((void**)&slotw, g_slotw);

    embed_kernel<<<(SS * DD) / 256, 256>>>(src, emb, x);

    for (int l = 0; l < NLAYER; l++) {
        const float* wi = in_proj_w  + (long)l * D3 * DD;
        const float* bi = in_proj_b  + (long)l * D3;
        const float* wo = out_proj_w + (long)l * DD * DD;
        const float* bo = out_proj_b + (long)l * DD;
        const float* gw = gate_w     + (long)l * EE * DD;
        const float* gb = gate_b     + (long)l * EE;
        const float* w1l = w1        + (long)l * EE * FF * DD;
        const float* b1l = b1        + (long)l * EE * FF;
        const float* w2l = w2        + (long)l * EE * DD * FF;
        const float* b2l = b2        + (long)l * EE * DD;

        // qkv = x @ wi^T + bi   [2048 x 3072], K=1024
        gemm_tc<<<dim3(SS/GBM, D3/GBN, 1), 256, GEMM_SMEM_BYTES>>>(x, wi, bi, qkv,
            SS, D3, DD, DD, DD, D3, 0, 0, 0, 0, 1.f, 0, 0);

        split_heads<<<(SS * DD) / 256, 256>>>(qkv, q, k, vt);

        // scores = q @ k^T / 8   batch=64, M=N=512, K=64, causal block skip
        gemm_tc<<<dim3(LL/GBM, LL/GBN, BB*HH), 256, GEMM_SMEM_BYTES>>>(q, k, nullptr, sc,
            LL, LL, HD, HD, HD, LL,
            (long)LL*HD, (long)LL*HD, (long)LL*LL, 0, 0.125f, 0, 1);

        softmax_causal<<<BB * HH * LL, 128>>>(sc);

        // av = attn @ vt^T   batch=64, M=512, N=64, K=512
        gemm_tc<<<dim3(LL/GBM, 1, BB*HH), 256, GEMM_SMEM_BYTES>>>(sc, vt, nullptr, av,
            LL, HD, LL, LL, LL, HD,
            (long)LL*LL, (long)HD*LL, (long)LL*HD, 0, 1.f, 0, 0);

        merge_heads<<<(SS * DD) / 256, 256>>>(av, attn);

        // proj = attn @ wo^T + bo   [2048 x 1024], K=1024
        gemm_tc<<<dim3(SS/GBM, DD/GBN, 1), 256, GEMM_SMEM_BYTES>>>(attn, wo, bo, tmp,
            SS, DD, DD, DD, DD, DD, 0, 0, 0, 0, 1.f, 0, 0);

        add_ln<<<SS, 256>>>(x, tmp, ln1_w + l * DD, ln1_b + l * DD, x);

        // ---- MoE ----
        gate_topk<<<SS, 256>>>(x, gw, gb, topi, topw);
        route_kernel<<<EE, 256>>>(topi, topw, slot, slotw);
        gather_xe<<<EE * CAP, 256>>>(x, slot, xe);

        // h = relu(xe @ w1^T + b1)   batch=8, M=320, N=4096, K=1024
        gemm_tc<<<dim3((CAP+GBM-1)/GBM, FF/GBN, EE), 256, GEMM_SMEM_BYTES>>>(xe, w1l, b1l, hbuf,
            CAP, FF, DD, DD, DD, FF,
            (long)CAP*DD, (long)FF*DD, (long)CAP*FF, FF, 1.f, 1, 0);

        // oe = h @ w2^T + b2   batch=8, M=320, N=1024, K=4096
        gemm_tc<<<dim3((CAP+GBM-1)/GBM, DD/GBN, EE), 256, GEMM_SMEM_BYTES>>>(hbuf, w2l, b2l, oe,
            CAP, DD, FF, FF, FF, DD,
            (long)CAP*FF, (long)DD*FF, (long)CAP*DD, DD, 1.f, 0, 0);

        cudaMemsetAsync(tmp, 0, (size_t)SS * DD * sizeof(float), 0);
        scatter_oe<<<EE * CAP, 256>>>(oe, slot, slotw, tmp);

        add_ln<<<SS, 256>>>(x, tmp, ln2_w + l * DD, ln2_b + l * DD, x);
    }

    // logits = x @ dec_w^T + dec_b   [2048 x 32000], K=1024
    gemm_tc<<<dim3(SS/GBM, (VV+GBN-1)/GBN, 1), 256, GEMM_SMEM_BYTES>>>(x, dec_w, dec_b, out,
        SS, VV, DD, DD, DD, VV, 0, 0, 0, 0, 1.f, 0, 0);
}